// round 1
// baseline (speedup 1.0000x reference)
#include <cuda_runtime.h>
#include <math.h>

#define LSEQ   2048
#define LFFT   4096
#define DMODEL 512
#define NSTATE 64
#define NBATCH 16
#define PI_F   3.14159265358979323846f

// Scratch (device globals — no runtime allocation allowed)
__device__ float2 g_Khat[DMODEL * LFFT];   // 16 MB: per-channel spectrum of padded K, pre-scaled by 1/LFFT
__device__ float2 g_tw[LFFT];              // stage-compacted twiddles: tw[Ns+base] = e^{-i*pi*base/Ns}

__device__ __forceinline__ float2 cmulf(float2 a, float2 b) {
    return make_float2(a.x * b.x - a.y * b.y, a.x * b.y + a.y * b.x);
}

// ---------------------------------------------------------------------------
// Twiddle table init: tw[Ns + base] = exp(-i*pi*base/Ns), Ns = 1,2,...,2048
// One table serves every stage of every power-of-two FFT up to 4096.
// ---------------------------------------------------------------------------
__global__ void init_tw_kernel() {
    int i = blockIdx.x * blockDim.x + threadIdx.x;
    if (i >= LFFT) return;
    if (i == 0) { g_tw[0] = make_float2(1.0f, 0.0f); return; }
    int k = 31 - __clz(i);
    int Ns = 1 << k;
    int base = i - Ns;
    float ang = -PI_F * (float)base / (float)Ns;
    float s, c;
    sincosf(ang, &s, &c);
    g_tw[i] = make_float2(c, s);
}

// ---------------------------------------------------------------------------
// In-smem Stockham radix-2 FFT, ping-pong between src/dst.
// tsign = +1.0f : forward DFT  (twiddles e^{-i...}, table as stored)
// tsign = -1.0f : inverse DFT  (conjugated twiddles), UNnormalized.
// Returns pointer to the buffer containing the result.
// Caller must __syncthreads() before calling (src fully written).
// ---------------------------------------------------------------------------
__device__ float2* fft_stockham(float2* src, float2* dst, int N, float tsign,
                                const float2* tw, int tid, int nth) {
    int half = N >> 1;
    int shift = 0;
    for (int Ns = 1; Ns < N; Ns <<= 1, shift++) {
        for (int j = tid; j < half; j += nth) {
            int base = j & (Ns - 1);
            float2 t = tw[Ns + base];
            float wx = t.x, wy = t.y * tsign;
            float2 a = src[j];
            float2 b = src[j + half];
            float2 bw = make_float2(b.x * wx - b.y * wy, b.x * wy + b.y * wx);
            int idx = ((j >> shift) << (shift + 1)) + base;
            dst[idx]      = make_float2(a.x + bw.x, a.y + bw.y);
            dst[idx + Ns] = make_float2(a.x - bw.x, a.y - bw.y);
        }
        __syncthreads();
        float2* tmp = src; src = dst; dst = tmp;
    }
    return src;
}

// ---------------------------------------------------------------------------
// Kernel 1: per channel d, evaluate the fused Cauchy kernel at the 2048 roots
// of unity, ifft -> K (real impulse response), zero-pad to 4096, forward FFT,
// store Khat (pre-scaled by 1/4096 so the conv kernel's inverse FFT needs no
// normalization).
// Singularity-free forms:  g = -i*(2/step)*tan(pi*l/L),  c = 1 - i*tan(pi*l/L)
// ---------------------------------------------------------------------------
__global__ void __launch_bounds__(512) khat_kernel(
    const float* __restrict__ pr, const float* __restrict__ qr,
    const float* __restrict__ lamr, const float* __restrict__ Br,
    const float* __restrict__ Ctr, const float* __restrict__ logstep) {
    extern __shared__ float2 sm[];
    float2* buf0 = sm;              // 4096
    float2* buf1 = sm + LFFT;       // 4096
    float2* tws  = sm + 2 * LFFT;   // 4096 twiddles

    __shared__ float2 w00[NSTATE], w01[NSTATE], w10[NSTATE], w11[NSTATE];
    __shared__ float2 lams[NSTATE];
    __shared__ float s_inv2step;

    int d = blockIdx.x;
    int tid = threadIdx.x;

    for (int i = tid; i < LFFT; i += blockDim.x) tws[i] = g_tw[i];

    if (tid < NSTATE) {
        int n = tid;
        float2 p  = make_float2(pr[2*n],  pr[2*n+1]);
        float2 qc = make_float2(qr[2*n], -qr[2*n+1]);                      // conj(q)
        float2 lm = make_float2(lamr[2*n], lamr[2*n+1]);
        float2 Bv = make_float2(Br[(d*NSTATE+n)*2],  Br[(d*NSTATE+n)*2+1]);
        float2 Cc = make_float2(Ctr[(d*NSTATE+n)*2], -Ctr[(d*NSTATE+n)*2+1]); // conj(Ct)
        w00[n] = cmulf(Cc, Bv);
        w01[n] = cmulf(Cc, p);
        w10[n] = cmulf(qc, Bv);
        w11[n] = cmulf(qc, p);
        lams[n] = lm;
    }
    if (tid == 0) s_inv2step = 2.0f * expf(-logstep[d]);
    __syncthreads();

    float inv2step = s_inv2step;

    // Each thread owns 4 frequency points; n-loop outer so weights are loaded
    // once per n (broadcast LDS) and reused across the 4 points.
    {
        float2 a00[4], a01[4], a10[4], a11[4];
        float  gims[4], ts[4];
        int    ls[4];
#pragma unroll
        for (int k = 0; k < 4; k++) {
            int l = tid + k * 512;
            ls[k] = l;
            float theta = (PI_F / (float)LSEQ) * (float)l;
            float t = tanf(theta);
            ts[k] = t;
            gims[k] = -inv2step * t;
            a00[k] = make_float2(0.f, 0.f);
            a01[k] = make_float2(0.f, 0.f);
            a10[k] = make_float2(0.f, 0.f);
            a11[k] = make_float2(0.f, 0.f);
        }
        for (int n = 0; n < NSTATE; n++) {
            float2 lw = lams[n];
            float2 v00 = w00[n], v01 = w01[n], v10 = w10[n], v11 = w11[n];
            float dr = -lw.x;
#pragma unroll
            for (int k = 0; k < 4; k++) {
                float di  = gims[k] - lw.y;
                float inv = __fdividef(1.0f, dr * dr + di * di);
                float rx = dr * inv, ry = -di * inv;
                a00[k].x += v00.x * rx - v00.y * ry;  a00[k].y += v00.x * ry + v00.y * rx;
                a01[k].x += v01.x * rx - v01.y * ry;  a01[k].y += v01.x * ry + v01.y * rx;
                a10[k].x += v10.x * rx - v10.y * ry;  a10[k].y += v10.x * ry + v10.y * rx;
                a11[k].x += v11.x * rx - v11.y * ry;  a11[k].y += v11.x * ry + v11.y * rx;
            }
        }
#pragma unroll
        for (int k = 0; k < 4; k++) {
            float2 den = make_float2(1.0f + a11[k].x, a11[k].y);
            float dinv = __fdividef(1.0f, den.x * den.x + den.y * den.y);
            float2 num = cmulf(a01[k], a10[k]);
            float2 frac = make_float2((num.x * den.x + num.y * den.y) * dinv,
                                      (num.y * den.x - num.x * den.y) * dinv);
            float2 inner = make_float2(a00[k].x - frac.x, a00[k].y - frac.y);
            float2 c = make_float2(1.0f, -ts[k]);
            buf0[ls[k]] = cmulf(c, inner);
        }
    }
    __syncthreads();

    // ifft_2048 (unnormalized inverse; 1/2048 folded into K extraction)
    float2* res = fft_stockham(buf0, buf1, LSEQ, -1.0f, tws, tid, blockDim.x);
    float2* oth = (res == buf0) ? buf1 : buf0;

    // K[m] = Re(out[(L-m) mod L]) / L   (ifft reorder [0, L-1, ..., 1]), zero-pad.
    const float invL = 1.0f / (float)LSEQ;
    for (int m = tid; m < LSEQ; m += blockDim.x) {
        float kr = res[(LSEQ - m) & (LSEQ - 1)].x * invL;
        oth[m]        = make_float2(kr, 0.0f);
        oth[m + LSEQ] = make_float2(0.0f, 0.0f);
    }
    __syncthreads();

    // forward FFT_4096 of padded K; store with 1/4096 (irfft norm) folded in.
    float2* res2 = fft_stockham(oth, res, LFFT, +1.0f, tws, tid, blockDim.x);
    const float invF = 1.0f / (float)LFFT;
    for (int k = tid; k < LFFT; k += blockDim.x) {
        float2 v = res2[k];
        g_Khat[d * LFFT + k] = make_float2(v.x * invF, v.y * invF);
    }
}

// ---------------------------------------------------------------------------
// Kernel 2: per (batch, channel-pair) block. Real-pair trick: z = u_{2p} + i*u_{2p+1}
// (a single float2 load from the [B,L,D] layout!), one forward FFT, spectrum
// split + pointwise multiply with the two Khat rows, one inverse FFT, write
// y + D*u as float2.
// ---------------------------------------------------------------------------
__global__ void __launch_bounds__(512) conv_kernel(
    const float* __restrict__ u, const float* __restrict__ Dvec,
    float* __restrict__ out) {
    extern __shared__ float2 sm[];
    float2* buf0 = sm;
    float2* buf1 = sm + LFFT;
    float2* tws  = sm + 2 * LFFT;

    int tid  = threadIdx.x;
    int blk  = blockIdx.x;
    int b    = blk & (NBATCH - 1);
    int pair = blk >> 4;
    int d0   = pair * 2;

    for (int i = tid; i < LFFT; i += blockDim.x) tws[i] = g_tw[i];

    const float2* uf2 = reinterpret_cast<const float2*>(u);
    const size_t ubase = (size_t)b * (size_t)(LSEQ * (DMODEL / 2)) + (size_t)pair;

    float2 ureg[4];
#pragma unroll
    for (int k = 0; k < 4; k++) {
        int l = tid + k * 512;
        float2 v = uf2[ubase + (size_t)l * (DMODEL / 2)];
        ureg[k] = v;
        buf0[l]        = v;                      // packed real pair
        buf0[l + LSEQ] = make_float2(0.f, 0.f);  // zero pad
    }
    __syncthreads();

    float2* Z = fft_stockham(buf0, buf1, LFFT, +1.0f, tws, tid, 512);
    float2* Y = (Z == buf0) ? buf1 : buf0;

    const float2* K0 = g_Khat + (size_t)d0 * LFFT;
    const float2* K1 = K0 + LFFT;
    for (int k = tid; k < LFFT; k += 512) {
        float2 z  = Z[k];
        float2 zm = Z[(LFFT - k) & (LFFT - 1)];
        // U0 = (Z[k]+conj(Z[-k]))/2 ;  U1 = -i*(Z[k]-conj(Z[-k]))/2
        float2 u0  = make_float2(0.5f * (z.x + zm.x), 0.5f * (z.y - zm.y));
        float2 iu1 = make_float2(0.5f * (z.x - zm.x), 0.5f * (z.y + zm.y));
        float2 u1  = make_float2(iu1.y, -iu1.x);
        float2 y0 = cmulf(u0, K0[k]);
        float2 y1 = cmulf(u1, K1[k]);
        // Y = Y0 + i*Y1  -> ifft gives y0 in real part, y1 in imag part
        Y[k] = make_float2(y0.x - y1.y, y0.y + y1.x);
    }
    __syncthreads();

    float2* yr = fft_stockham(Y, Z, LFFT, -1.0f, tws, tid, 512); // norm folded into Khat

    float D0 = Dvec[d0], D1 = Dvec[d0 + 1];
    float2* of2 = reinterpret_cast<float2*>(out);
#pragma unroll
    for (int k = 0; k < 4; k++) {
        int l = tid + k * 512;
        float2 y = yr[l];
        of2[ubase + (size_t)l * (DMODEL / 2)] =
            make_float2(y.x + D0 * ureg[k].x, y.y + D1 * ureg[k].y);
    }
}

// ---------------------------------------------------------------------------
// Launch. Inputs (metadata order): u, p_ri, q_ri, lam_ri, B_ri, Ct_ri, D, log_step
// ---------------------------------------------------------------------------
extern "C" void kernel_launch(void* const* d_in, const int* in_sizes, int n_in,
                              void* d_out, int out_size) {
    const float* u   = (const float*)d_in[0];
    const float* pr  = (const float*)d_in[1];
    const float* qr  = (const float*)d_in[2];
    const float* lam = (const float*)d_in[3];
    const float* Br  = (const float*)d_in[4];
    const float* Ct  = (const float*)d_in[5];
    const float* Dv  = (const float*)d_in[6];
    const float* ls  = (const float*)d_in[7];
    float* out = (float*)d_out;

    const int smem_bytes = 3 * LFFT * (int)sizeof(float2);   // 96 KB
    cudaFuncSetAttribute(khat_kernel, cudaFuncAttributeMaxDynamicSharedMemorySize, smem_bytes);
    cudaFuncSetAttribute(conv_kernel, cudaFuncAttributeMaxDynamicSharedMemorySize, smem_bytes);

    init_tw_kernel<<<LFFT / 512, 512>>>();
    khat_kernel<<<DMODEL, 512, smem_bytes>>>(pr, qr, lam, Br, Ct, ls);
    conv_kernel<<<NBATCH * (DMODEL / 2), 512, smem_bytes>>>(u, Dv, out);
}

// round 2
// speedup vs baseline: 1.5841x; 1.5841x over previous
#include <cuda_runtime.h>
#include <math.h>

#define LSEQ   2048
#define LFFT   4096
#define DMODEL 512
#define NSTATE 64
#define NBATCH 16
#define PI_F   3.14159265358979323846f

// XOR smem swizzle: folds bits [3:7) into [0:4). Bijective, block-local.
// Makes stride-{1,8,64,256,512} float2 access patterns half-warp conflict-free.
#define SWZ(i) ((i) ^ (((i) >> 3) & 15))

__device__ float2 g_Khat[DMODEL * LFFT];   // 16 MB, Khat pre-scaled by 1/LFFT
__device__ float2 g_tw[LFFT];              // tw[Ns+base] = e^{-i*pi*base/Ns}

__device__ __forceinline__ float2 cmulf(float2 a, float2 b) {
    return make_float2(a.x * b.x - a.y * b.y, a.x * b.y + a.y * b.x);
}
__device__ __forceinline__ float2 cadd(float2 a, float2 b) { return make_float2(a.x + b.x, a.y + b.y); }
__device__ __forceinline__ float2 csub(float2 a, float2 b) { return make_float2(a.x - b.x, a.y - b.y); }

template<bool FWD> __device__ __forceinline__ float2 mul_j(float2 a) {   // *(-i) fwd, *(+i) inv
    return FWD ? make_float2(a.y, -a.x) : make_float2(-a.y, a.x);
}
template<bool FWD> __device__ __forceinline__ float2 mul_w1(float2 a) {  // *e^{-ipi/4} fwd
    const float C = 0.70710678118654752f;
    return FWD ? make_float2(C * (a.x + a.y), C * (a.y - a.x))
               : make_float2(C * (a.x - a.y), C * (a.x + a.y));
}
template<bool FWD> __device__ __forceinline__ float2 mul_w3(float2 a) {  // *e^{-3ipi/4} fwd
    const float C = 0.70710678118654752f;
    return FWD ? make_float2(C * (a.y - a.x), -C * (a.x + a.y))
               : make_float2(-C * (a.x + a.y), C * (a.x - a.y));
}

// 8-point DFT, natural order in and out (DIF with bit-reversal folded into outputs)
template<bool FWD>
__device__ __forceinline__ void fft8(float2* v) {
    float2 t0 = cadd(v[0], v[4]), t4 = csub(v[0], v[4]);
    float2 t1 = cadd(v[1], v[5]), t5 = mul_w1<FWD>(csub(v[1], v[5]));
    float2 t2 = cadd(v[2], v[6]), t6 = mul_j<FWD>(csub(v[2], v[6]));
    float2 t3 = cadd(v[3], v[7]), t7 = mul_w3<FWD>(csub(v[3], v[7]));
    float2 u0 = cadd(t0, t2), u2 = csub(t0, t2);
    float2 u1 = cadd(t1, t3), u3 = mul_j<FWD>(csub(t1, t3));
    float2 u4 = cadd(t4, t6), u6 = csub(t4, t6);
    float2 u5 = cadd(t5, t7), u7 = mul_j<FWD>(csub(t5, t7));
    v[0] = cadd(u0, u1); v[4] = csub(u0, u1);
    v[2] = cadd(u2, u3); v[6] = csub(u2, u3);
    v[1] = cadd(u4, u5); v[5] = csub(u4, u5);
    v[3] = cadd(u6, u7); v[7] = csub(u6, u7);
}

template<bool FWD>
__device__ __forceinline__ void fft4(float2* v) {
    float2 t0 = cadd(v[0], v[2]), t2 = csub(v[0], v[2]);
    float2 t1 = cadd(v[1], v[3]), t3 = mul_j<FWD>(csub(v[1], v[3]));
    v[0] = cadd(t0, t1); v[2] = csub(t0, t1);
    v[1] = cadd(t2, t3); v[3] = csub(t2, t3);
}

// ---------------------------------------------------------------------------
// 4096-point FFT: 4 radix-8 Stockham stages, butterflies in registers,
// ping-pong smem, all smem accesses through SWZ. Twiddles from L1-resident
// global table. Caller syncs before; result buffer returned (4 swaps -> src).
// ---------------------------------------------------------------------------
template<bool FWD>
__device__ float2* fft4096_r8(float2* src, float2* dst, int tid, int nth) {
#pragma unroll
    for (int s = 0; s < 4; s++) {
        const int Ns = 1 << (3 * s);
        for (int j = tid; j < 512; j += nth) {
            float2 v[8];
#pragma unroll
            for (int r = 0; r < 8; r++) v[r] = src[SWZ(j + r * 512)];
            const int base = j & (Ns - 1);
            if (Ns > 1) {
                float2 w1 = g_tw[4 * Ns + base];
                float2 w2 = g_tw[2 * Ns + base];
                float2 w4 = g_tw[Ns + base];
                if (!FWD) { w1.y = -w1.y; w2.y = -w2.y; w4.y = -w4.y; }
                float2 w3 = cmulf(w1, w2), w5 = cmulf(w1, w4);
                float2 w6 = cmulf(w2, w4), w7 = cmulf(w3, w4);
                v[1] = cmulf(v[1], w1); v[2] = cmulf(v[2], w2); v[3] = cmulf(v[3], w3);
                v[4] = cmulf(v[4], w4); v[5] = cmulf(v[5], w5); v[6] = cmulf(v[6], w6);
                v[7] = cmulf(v[7], w7);
            }
            fft8<FWD>(v);
            const int idxD = ((j - base) << 3) + base;
#pragma unroll
            for (int r = 0; r < 8; r++) dst[SWZ(idxD + r * Ns)] = v[r];
        }
        __syncthreads();
        float2* t = src; src = dst; dst = t;
    }
    return src;
}

// 2048-point inverse FFT (unnormalized): 3 radix-8 stages + 1 radix-4 stage.
__device__ float2* ifft2048_mr(float2* src, float2* dst, int tid, int nth) {
#pragma unroll
    for (int s = 0; s < 3; s++) {
        const int Ns = 1 << (3 * s);
        for (int j = tid; j < 256; j += nth) {
            float2 v[8];
#pragma unroll
            for (int r = 0; r < 8; r++) v[r] = src[SWZ(j + r * 256)];
            const int base = j & (Ns - 1);
            if (Ns > 1) {
                float2 w1 = g_tw[4 * Ns + base];
                float2 w2 = g_tw[2 * Ns + base];
                float2 w4 = g_tw[Ns + base];
                w1.y = -w1.y; w2.y = -w2.y; w4.y = -w4.y;
                float2 w3 = cmulf(w1, w2), w5 = cmulf(w1, w4);
                float2 w6 = cmulf(w2, w4), w7 = cmulf(w3, w4);
                v[1] = cmulf(v[1], w1); v[2] = cmulf(v[2], w2); v[3] = cmulf(v[3], w3);
                v[4] = cmulf(v[4], w4); v[5] = cmulf(v[5], w5); v[6] = cmulf(v[6], w6);
                v[7] = cmulf(v[7], w7);
            }
            fft8<false>(v);
            const int idxD = ((j - base) << 3) + base;
#pragma unroll
            for (int r = 0; r < 8; r++) dst[SWZ(idxD + r * Ns)] = v[r];
        }
        __syncthreads();
        float2* t = src; src = dst; dst = t;
    }
    // final radix-4 stage, Ns = 512
    for (int j = tid; j < 512; j += nth) {
        float2 v[4];
#pragma unroll
        for (int r = 0; r < 4; r++) v[r] = src[SWZ(j + r * 512)];
        float2 w1 = g_tw[1024 + j]; w1.y = -w1.y;
        float2 w2 = g_tw[512 + j];  w2.y = -w2.y;
        float2 w3 = cmulf(w1, w2);
        v[1] = cmulf(v[1], w1); v[2] = cmulf(v[2], w2); v[3] = cmulf(v[3], w3);
        fft4<false>(v);
#pragma unroll
        for (int r = 0; r < 4; r++) dst[SWZ(j + r * 512)] = v[r];
    }
    __syncthreads();
    return dst;
}

__global__ void init_tw_kernel() {
    int i = blockIdx.x * blockDim.x + threadIdx.x;
    if (i >= LFFT) return;
    if (i == 0) { g_tw[0] = make_float2(1.0f, 0.0f); return; }
    int k = 31 - __clz(i);
    int Ns = 1 << k;
    int base = i - Ns;
    float ang = -PI_F * (float)base / (float)Ns;
    float s, c;
    sincosf(ang, &s, &c);
    g_tw[i] = make_float2(c, s);
}

// ---------------------------------------------------------------------------
// Kernel 1: Cauchy kernel at 2048 roots of unity -> ifft2048 -> K -> pad ->
// fft4096 -> Khat (pre-scaled by 1/4096). Singularity-free tan forms.
// ---------------------------------------------------------------------------
__global__ void __launch_bounds__(512, 2) khat_kernel(
    const float* __restrict__ pr, const float* __restrict__ qr,
    const float* __restrict__ lamr, const float* __restrict__ Br,
    const float* __restrict__ Ctr, const float* __restrict__ logstep) {
    extern __shared__ float2 sm[];
    float2* buf0 = sm;
    float2* buf1 = sm + LFFT;

    __shared__ float2 w00[NSTATE], w01[NSTATE], w10[NSTATE], w11[NSTATE];
    __shared__ float2 lams[NSTATE];
    __shared__ float s_inv2step;

    int d = blockIdx.x;
    int tid = threadIdx.x;

    if (tid < NSTATE) {
        int n = tid;
        float2 p  = make_float2(pr[2*n],  pr[2*n+1]);
        float2 qc = make_float2(qr[2*n], -qr[2*n+1]);
        float2 lm = make_float2(lamr[2*n], lamr[2*n+1]);
        float2 Bv = make_float2(Br[(d*NSTATE+n)*2],  Br[(d*NSTATE+n)*2+1]);
        float2 Cc = make_float2(Ctr[(d*NSTATE+n)*2], -Ctr[(d*NSTATE+n)*2+1]);
        w00[n] = cmulf(Cc, Bv);
        w01[n] = cmulf(Cc, p);
        w10[n] = cmulf(qc, Bv);
        w11[n] = cmulf(qc, p);
        lams[n] = lm;
    }
    if (tid == 0) s_inv2step = 2.0f * expf(-logstep[d]);
    __syncthreads();

    float inv2step = s_inv2step;
    {
        float2 a00[4], a01[4], a10[4], a11[4];
        float  gims[4], ts[4];
#pragma unroll
        for (int k = 0; k < 4; k++) {
            int l = tid + k * 512;
            float theta = (PI_F / (float)LSEQ) * (float)l;
            float t = tanf(theta);
            ts[k] = t;
            gims[k] = -inv2step * t;
            a00[k] = make_float2(0.f, 0.f);
            a01[k] = make_float2(0.f, 0.f);
            a10[k] = make_float2(0.f, 0.f);
            a11[k] = make_float2(0.f, 0.f);
        }
        for (int n = 0; n < NSTATE; n++) {
            float2 lw = lams[n];
            float2 v00 = w00[n], v01 = w01[n], v10 = w10[n], v11 = w11[n];
            float dr = -lw.x;
#pragma unroll
            for (int k = 0; k < 4; k++) {
                float di  = gims[k] - lw.y;
                float inv = __fdividef(1.0f, dr * dr + di * di);
                float rx = dr * inv, ry = -di * inv;
                a00[k].x += v00.x * rx - v00.y * ry;  a00[k].y += v00.x * ry + v00.y * rx;
                a01[k].x += v01.x * rx - v01.y * ry;  a01[k].y += v01.x * ry + v01.y * rx;
                a10[k].x += v10.x * rx - v10.y * ry;  a10[k].y += v10.x * ry + v10.y * rx;
                a11[k].x += v11.x * rx - v11.y * ry;  a11[k].y += v11.x * ry + v11.y * rx;
            }
        }
#pragma unroll
        for (int k = 0; k < 4; k++) {
            int l = tid + k * 512;
            float2 den = make_float2(1.0f + a11[k].x, a11[k].y);
            float dinv = __fdividef(1.0f, den.x * den.x + den.y * den.y);
            float2 num = cmulf(a01[k], a10[k]);
            float2 frac = make_float2((num.x * den.x + num.y * den.y) * dinv,
                                      (num.y * den.x - num.x * den.y) * dinv);
            float2 inner = make_float2(a00[k].x - frac.x, a00[k].y - frac.y);
            float2 c = make_float2(1.0f, -ts[k]);
            buf0[SWZ(l)] = cmulf(c, inner);
        }
    }
    __syncthreads();

    float2* res = ifft2048_mr(buf0, buf1, tid, 512);
    float2* oth = (res == buf0) ? buf1 : buf0;

    const float invL = 1.0f / (float)LSEQ;
    for (int m = tid; m < LSEQ; m += 512) {
        float kr = res[SWZ((LSEQ - m) & (LSEQ - 1))].x * invL;
        oth[SWZ(m)]        = make_float2(kr, 0.0f);
        oth[SWZ(m + LSEQ)] = make_float2(0.0f, 0.0f);
    }
    __syncthreads();

    float2* res2 = fft4096_r8<true>(oth, res, tid, 512);
    const float invF = 1.0f / (float)LFFT;
    for (int k = tid; k < LFFT; k += 512) {
        float2 v = res2[SWZ(k)];
        g_Khat[d * LFFT + k] = make_float2(v.x * invF, v.y * invF);
    }
}

// ---------------------------------------------------------------------------
// Kernel 2: one (batch, channel-pair) per block, 256 threads. Real-pair
// packing -> one fwd FFT4096, spectrum split + multiply, one inv FFT4096.
// ---------------------------------------------------------------------------
__global__ void __launch_bounds__(256) conv_kernel(
    const float* __restrict__ u, const float* __restrict__ Dvec,
    float* __restrict__ out) {
    extern __shared__ float2 sm[];
    float2* buf0 = sm;
    float2* buf1 = sm + LFFT;

    int tid  = threadIdx.x;
    int blk  = blockIdx.x;
    int pair = blk & (DMODEL / 2 - 1);   // adjacent blocks -> adjacent pairs (L2 dedup)
    int b    = blk >> 8;
    int d0   = pair * 2;

    const float2* uf2 = reinterpret_cast<const float2*>(u);
    const size_t ubase = (size_t)b * (size_t)(LSEQ * (DMODEL / 2)) + (size_t)pair;

#pragma unroll
    for (int k = 0; k < 16; k++) {
        int l = tid + k * 256;
        if (k < 8) {
            buf0[SWZ(l)] = uf2[ubase + (size_t)l * (DMODEL / 2)];
        } else {
            buf0[SWZ(l)] = make_float2(0.f, 0.f);
        }
    }
    __syncthreads();

    float2* Z = fft4096_r8<true>(buf0, buf1, tid, 256);
    float2* Y = (Z == buf0) ? buf1 : buf0;

    const float2* K0 = g_Khat + (size_t)d0 * LFFT;
    const float2* K1 = K0 + LFFT;
#pragma unroll 4
    for (int m = 0; m < 16; m++) {
        int k = tid + m * 256;
        float2 z  = Z[SWZ(k)];
        float2 zm = Z[SWZ((LFFT - k) & (LFFT - 1))];
        float2 u0  = make_float2(0.5f * (z.x + zm.x), 0.5f * (z.y - zm.y));
        float2 iu1 = make_float2(0.5f * (z.x - zm.x), 0.5f * (z.y + zm.y));
        float2 u1  = make_float2(iu1.y, -iu1.x);
        float2 y0 = cmulf(u0, K0[k]);
        float2 y1 = cmulf(u1, K1[k]);
        Y[SWZ(k)] = make_float2(y0.x - y1.y, y0.y + y1.x);
    }
    __syncthreads();

    float2* yr = fft4096_r8<false>(Y, Z, tid, 256);   // norm folded into Khat

    float D0 = Dvec[d0], D1 = Dvec[d0 + 1];
    float2* of2 = reinterpret_cast<float2*>(out);
#pragma unroll
    for (int k = 0; k < 8; k++) {
        int l = tid + k * 256;
        float2 y = yr[SWZ(l)];
        float2 uv = uf2[ubase + (size_t)l * (DMODEL / 2)];
        of2[ubase + (size_t)l * (DMODEL / 2)] =
            make_float2(y.x + D0 * uv.x, y.y + D1 * uv.y);
    }
}

// ---------------------------------------------------------------------------
// Inputs: u, p_ri, q_ri, lam_ri, B_ri, Ct_ri, D, log_step
// ---------------------------------------------------------------------------
extern "C" void kernel_launch(void* const* d_in, const int* in_sizes, int n_in,
                              void* d_out, int out_size) {
    const float* u   = (const float*)d_in[0];
    const float* pr  = (const float*)d_in[1];
    const float* qr  = (const float*)d_in[2];
    const float* lam = (const float*)d_in[3];
    const float* Br  = (const float*)d_in[4];
    const float* Ct  = (const float*)d_in[5];
    const float* Dv  = (const float*)d_in[6];
    const float* ls  = (const float*)d_in[7];
    float* out = (float*)d_out;

    const int smem_bytes = 2 * LFFT * (int)sizeof(float2);   // 64 KB
    cudaFuncSetAttribute(khat_kernel, cudaFuncAttributeMaxDynamicSharedMemorySize, smem_bytes);
    cudaFuncSetAttribute(conv_kernel, cudaFuncAttributeMaxDynamicSharedMemorySize, smem_bytes);

    init_tw_kernel<<<LFFT / 512, 512>>>();
    khat_kernel<<<DMODEL, 512, smem_bytes>>>(pr, qr, lam, Br, Ct, ls);
    conv_kernel<<<NBATCH * (DMODEL / 2), 256, smem_bytes>>>(u, Dv, out);
}

// round 3
// speedup vs baseline: 1.6327x; 1.0306x over previous
#include <cuda_runtime.h>
#include <math.h>

#define LSEQ   2048
#define LFFT   4096
#define DMODEL 512
#define NSTATE 64
#define NBATCH 16
#define PI_F   3.14159265358979323846f

// float2-granularity swizzle (khat kernel, unchanged from R2)
#define SWZ(i) ((i) ^ (((i) >> 3) & 15))
// float4-granularity swizzle (conv kernel)
#define SW4(e) ((e) ^ (((e) >> 3) & 7))

__device__ float2 g_Khat[DMODEL * LFFT];   // Khat, pre-scaled by 1/LFFT
__device__ float4 g_twd[LFFT];             // (c, s, -s, c); idx Ns+base -> e^{-i*pi*base/Ns}

__device__ __forceinline__ float2 cmulf(float2 a, float2 b) {
    return make_float2(a.x * b.x - a.y * b.y, a.x * b.y + a.y * b.x);
}
__device__ __forceinline__ float2 cadd(float2 a, float2 b) { return make_float2(a.x + b.x, a.y + b.y); }
__device__ __forceinline__ float2 csub(float2 a, float2 b) { return make_float2(a.x - b.x, a.y - b.y); }
// v * w where wn=(c,s), wr=(-s,c) (forward) or conjugated forms (inverse)
__device__ __forceinline__ float2 cmulF(float2 v, float2 wn, float2 wr) {
    return make_float2(v.x * wn.x + v.y * wr.x, v.x * wn.y + v.y * wr.y);
}

template<bool FWD> __device__ __forceinline__ float2 mul_j(float2 a) {
    return FWD ? make_float2(a.y, -a.x) : make_float2(-a.y, a.x);
}
template<bool FWD> __device__ __forceinline__ float2 mul_w1(float2 a) {
    const float C = 0.70710678118654752f;
    return FWD ? make_float2(C * (a.x + a.y), C * (a.y - a.x))
               : make_float2(C * (a.x - a.y), C * (a.x + a.y));
}
template<bool FWD> __device__ __forceinline__ float2 mul_w3(float2 a) {
    const float C = 0.70710678118654752f;
    return FWD ? make_float2(C * (a.y - a.x), -C * (a.x + a.y))
               : make_float2(-C * (a.x + a.y), C * (a.x - a.y));
}

template<bool FWD>
__device__ __forceinline__ void fft8(float2* v) {
    float2 t0 = cadd(v[0], v[4]), t4 = csub(v[0], v[4]);
    float2 t1 = cadd(v[1], v[5]), t5 = mul_w1<FWD>(csub(v[1], v[5]));
    float2 t2 = cadd(v[2], v[6]), t6 = mul_j<FWD>(csub(v[2], v[6]));
    float2 t3 = cadd(v[3], v[7]), t7 = mul_w3<FWD>(csub(v[3], v[7]));
    float2 u0 = cadd(t0, t2), u2 = csub(t0, t2);
    float2 u1 = cadd(t1, t3), u3 = mul_j<FWD>(csub(t1, t3));
    float2 u4 = cadd(t4, t6), u6 = csub(t4, t6);
    float2 u5 = cadd(t5, t7), u7 = mul_j<FWD>(csub(t5, t7));
    v[0] = cadd(u0, u1); v[4] = csub(u0, u1);
    v[2] = cadd(u2, u3); v[6] = csub(u2, u3);
    v[1] = cadd(u4, u5); v[5] = csub(u4, u5);
    v[3] = cadd(u6, u7); v[7] = csub(u6, u7);
}

template<bool FWD>
__device__ __forceinline__ void fft4(float2* v) {
    float2 t0 = cadd(v[0], v[2]), t2 = csub(v[0], v[2]);
    float2 t1 = cadd(v[1], v[3]), t3 = mul_j<FWD>(csub(v[1], v[3]));
    v[0] = cadd(t0, t1); v[2] = csub(t0, t1);
    v[1] = cadd(t2, t3); v[3] = csub(t2, t3);
}

// Build w1..w7 (normal+rotated forms) from three table entries, apply to v[1..7].
template<bool INV>
__device__ __forceinline__ void twapply8(float2* v, float4 W1, float4 W2, float4 W4) {
    float2 w1n, w1r, w2n, w2r, w4n, w4r;
    if (!INV) {
        w1n = make_float2(W1.x, W1.y); w1r = make_float2(W1.z, W1.w);
        w2n = make_float2(W2.x, W2.y); w2r = make_float2(W2.z, W2.w);
        w4n = make_float2(W4.x, W4.y); w4r = make_float2(W4.z, W4.w);
    } else {
        w1n = make_float2(W1.x, -W1.y); w1r = make_float2(-W1.z, W1.w);
        w2n = make_float2(W2.x, -W2.y); w2r = make_float2(-W2.z, W2.w);
        w4n = make_float2(W4.x, -W4.y); w4r = make_float2(-W4.z, W4.w);
    }
    float2 w3n = cmulF(w2n, w1n, w1r); float2 w3r = make_float2(-w3n.y, w3n.x);
    float2 w5n = cmulF(w4n, w1n, w1r); float2 w5r = make_float2(-w5n.y, w5n.x);
    float2 w6n = cmulF(w4n, w2n, w2r); float2 w6r = make_float2(-w6n.y, w6n.x);
    float2 w7n = cmulF(w4n, w3n, w3r); float2 w7r = make_float2(-w7n.y, w7n.x);
    v[1] = cmulF(v[1], w1n, w1r); v[2] = cmulF(v[2], w2n, w2r); v[3] = cmulF(v[3], w3n, w3r);
    v[4] = cmulF(v[4], w4n, w4r); v[5] = cmulF(v[5], w5n, w5r); v[6] = cmulF(v[6], w6n, w6r);
    v[7] = cmulF(v[7], w7n, w7r);
}

// ---------------------------------------------------------------------------
// One radix-8 Stockham stage over 4096 points, float4 smem, thread owns
// j-pair (2t, 2t+1). Reads: float4 element t+256r (SW4-linear). Ends with sync.
// ---------------------------------------------------------------------------
template<int NS, bool INV>
__device__ __forceinline__ void conv_stage(float4* sBuf, int cur, int t, int tS) {
    const float4* src = sBuf + cur * 2048;
    float4* dst = sBuf + (cur ^ 1) * 2048;
    float2 v0[8], v1[8];
#pragma unroll
    for (int r = 0; r < 8; r++) {
        float4 z = src[tS + 256 * r];
        v0[r] = make_float2(z.x, z.y);
        v1[r] = make_float2(z.z, z.w);
    }
    if (NS > 1) {
        int base0 = (2 * t) & (NS - 1);
        float4 W1a = g_twd[4 * NS + base0],     W2a = g_twd[2 * NS + base0],     W4a = g_twd[NS + base0];
        float4 W1b = g_twd[4 * NS + base0 + 1], W2b = g_twd[2 * NS + base0 + 1], W4b = g_twd[NS + base0 + 1];
        twapply8<INV>(v0, W1a, W2a, W4a);
        twapply8<INV>(v1, W1b, W2b, W4b);
    }
    fft8<!INV>(v0); fft8<!INV>(v1);
    if (NS == 1) {
#pragma unroll
        for (int m = 0; m < 4; m++) {
            dst[SW4(8 * t + m)]     = make_float4(v0[2*m].x, v0[2*m].y, v0[2*m+1].x, v0[2*m+1].y);
            dst[SW4(8 * t + 4 + m)] = make_float4(v1[2*m].x, v1[2*m].y, v1[2*m+1].x, v1[2*m+1].y);
        }
    } else {
        int base0 = (2 * t) & (NS - 1);
        int eBase = ((2 * t - base0) << 2) + (base0 >> 1);
#pragma unroll
        for (int r = 0; r < 8; r++)
            dst[SW4(eBase + (NS >> 1) * r)] = make_float4(v0[r].x, v0[r].y, v1[r].x, v1[r].y);
    }
    __syncthreads();
}

// pointwise: given Z[k], Z[-k], K0[k], K1[k] -> Y[k] (two real channels packed)
__device__ __forceinline__ float2 pwone(float2 z, float2 zm, float2 K0k, float2 K1k) {
    float2 u0  = make_float2(0.5f * (z.x + zm.x), 0.5f * (z.y - zm.y));
    float2 iu1 = make_float2(0.5f * (z.x - zm.x), 0.5f * (z.y + zm.y));
    float2 u1  = make_float2(iu1.y, -iu1.x);
    float2 y0 = cmulf(u0, K0k);
    float2 y1 = cmulf(u1, K1k);
    return make_float2(y0.x - y1.y, y0.y + y1.x);
}

// inverse stage 0 with the spectrum multiply fused into the loads
__device__ __forceinline__ void inv_stage0_pw(float4* sBuf, int cur, int t, int tS,
                                              const float4* K0, const float4* K1) {
    const float4* src = sBuf + cur * 2048;
    const float2* srcF2 = reinterpret_cast<const float2*>(src);
    float4* dst = sBuf + (cur ^ 1) * 2048;
    float2 v0[8], v1[8];
    // SW4(mA-256r) = SW4(mA)-256r (low-3 XOR unaffected by 256r); same for mB
    int sA0 = SW4(2048 - t);   // mirror element for k=2e (slot 0); t=0,r=0 handled below
    int sB0 = SW4(2047 - t);   // mirror element for k=2e+1 (slot 1)
#pragma unroll
    for (int r = 0; r < 8; r++) {
        float4 z4 = src[tS + 256 * r];
        float2 z1 = make_float2(z4.x, z4.y);
        float2 z2 = make_float2(z4.z, z4.w);
        int e = t + 256 * r;
        float2 zm1 = (e == 0) ? z1 : srcF2[(sA0 - 256 * r) * 2];
        float2 zm2 = srcF2[(sB0 - 256 * r) * 2 + 1];
        float4 k0 = K0[e];
        float4 k1 = K1[e];
        v0[r] = pwone(z1, zm1, make_float2(k0.x, k0.y), make_float2(k1.x, k1.y));
        v1[r] = pwone(z2, zm2, make_float2(k0.z, k0.w), make_float2(k1.z, k1.w));
    }
    fft8<false>(v0); fft8<false>(v1);
#pragma unroll
    for (int m = 0; m < 4; m++) {
        dst[SW4(8 * t + m)]     = make_float4(v0[2*m].x, v0[2*m].y, v0[2*m+1].x, v0[2*m+1].y);
        dst[SW4(8 * t + 4 + m)] = make_float4(v1[2*m].x, v1[2*m].y, v1[2*m+1].x, v1[2*m+1].y);
    }
    __syncthreads();
}

__global__ void init_twd_kernel() {
    int i = blockIdx.x * blockDim.x + threadIdx.x;
    if (i >= LFFT) return;
    if (i == 0) { g_twd[0] = make_float4(1.0f, 0.0f, 0.0f, 1.0f); return; }
    int k = 31 - __clz(i);
    int Ns = 1 << k;
    int base = i - Ns;
    float ang = -PI_F * (float)base / (float)Ns;
    float s, c;
    sincosf(ang, &s, &c);
    g_twd[i] = make_float4(c, s, -s, c);
}

__global__ void pad_kernel() {}

// ---------------------------------------------------------------------------
// khat kernel: R2 version (float2 smem, radix-8), reading g_twd.xy
// ---------------------------------------------------------------------------
template<bool FWD>
__device__ float2* fft4096_r8(float2* src, float2* dst, int tid, int nth) {
#pragma unroll
    for (int s = 0; s < 4; s++) {
        const int Ns = 1 << (3 * s);
        for (int j = tid; j < 512; j += nth) {
            float2 v[8];
#pragma unroll
            for (int r = 0; r < 8; r++) v[r] = src[SWZ(j + r * 512)];
            const int base = j & (Ns - 1);
            if (Ns > 1) {
                float4 T1 = g_twd[4 * Ns + base];
                float4 T2 = g_twd[2 * Ns + base];
                float4 T4 = g_twd[Ns + base];
                float2 w1 = make_float2(T1.x, FWD ? T1.y : -T1.y);
                float2 w2 = make_float2(T2.x, FWD ? T2.y : -T2.y);
                float2 w4 = make_float2(T4.x, FWD ? T4.y : -T4.y);
                float2 w3 = cmulf(w1, w2), w5 = cmulf(w1, w4);
                float2 w6 = cmulf(w2, w4), w7 = cmulf(w3, w4);
                v[1] = cmulf(v[1], w1); v[2] = cmulf(v[2], w2); v[3] = cmulf(v[3], w3);
                v[4] = cmulf(v[4], w4); v[5] = cmulf(v[5], w5); v[6] = cmulf(v[6], w6);
                v[7] = cmulf(v[7], w7);
            }
            fft8<FWD>(v);
            const int idxD = ((j - base) << 3) + base;
#pragma unroll
            for (int r = 0; r < 8; r++) dst[SWZ(idxD + r * Ns)] = v[r];
        }
        __syncthreads();
        float2* t = src; src = dst; dst = t;
    }
    return src;
}

__device__ float2* ifft2048_mr(float2* src, float2* dst, int tid, int nth) {
#pragma unroll
    for (int s = 0; s < 3; s++) {
        const int Ns = 1 << (3 * s);
        for (int j = tid; j < 256; j += nth) {
            float2 v[8];
#pragma unroll
            for (int r = 0; r < 8; r++) v[r] = src[SWZ(j + r * 256)];
            const int base = j & (Ns - 1);
            if (Ns > 1) {
                float4 T1 = g_twd[4 * Ns + base];
                float4 T2 = g_twd[2 * Ns + base];
                float4 T4 = g_twd[Ns + base];
                float2 w1 = make_float2(T1.x, -T1.y);
                float2 w2 = make_float2(T2.x, -T2.y);
                float2 w4 = make_float2(T4.x, -T4.y);
                float2 w3 = cmulf(w1, w2), w5 = cmulf(w1, w4);
                float2 w6 = cmulf(w2, w4), w7 = cmulf(w3, w4);
                v[1] = cmulf(v[1], w1); v[2] = cmulf(v[2], w2); v[3] = cmulf(v[3], w3);
                v[4] = cmulf(v[4], w4); v[5] = cmulf(v[5], w5); v[6] = cmulf(v[6], w6);
                v[7] = cmulf(v[7], w7);
            }
            fft8<false>(v);
            const int idxD = ((j - base) << 3) + base;
#pragma unroll
            for (int r = 0; r < 8; r++) dst[SWZ(idxD + r * Ns)] = v[r];
        }
        __syncthreads();
        float2* t = src; src = dst; dst = t;
    }
    for (int j = tid; j < 512; j += nth) {
        float2 v[4];
#pragma unroll
        for (int r = 0; r < 4; r++) v[r] = src[SWZ(j + r * 512)];
        float4 T1 = g_twd[1024 + j];
        float4 T2 = g_twd[512 + j];
        float2 w1 = make_float2(T1.x, -T1.y);
        float2 w2 = make_float2(T2.x, -T2.y);
        float2 w3 = cmulf(w1, w2);
        v[1] = cmulf(v[1], w1); v[2] = cmulf(v[2], w2); v[3] = cmulf(v[3], w3);
        fft4<false>(v);
#pragma unroll
        for (int r = 0; r < 4; r++) dst[SWZ(j + r * 512)] = v[r];
    }
    __syncthreads();
    return dst;
}

__global__ void __launch_bounds__(512, 2) khat_kernel(
    const float* __restrict__ pr, const float* __restrict__ qr,
    const float* __restrict__ lamr, const float* __restrict__ Br,
    const float* __restrict__ Ctr, const float* __restrict__ logstep) {
    extern __shared__ float2 sm[];
    float2* buf0 = sm;
    float2* buf1 = sm + LFFT;

    __shared__ float2 w00[NSTATE], w01[NSTATE], w10[NSTATE], w11[NSTATE];
    __shared__ float2 lams[NSTATE];
    __shared__ float s_inv2step;

    int d = blockIdx.x;
    int tid = threadIdx.x;

    if (tid < NSTATE) {
        int n = tid;
        float2 p  = make_float2(pr[2*n],  pr[2*n+1]);
        float2 qc = make_float2(qr[2*n], -qr[2*n+1]);
        float2 lm = make_float2(lamr[2*n], lamr[2*n+1]);
        float2 Bv = make_float2(Br[(d*NSTATE+n)*2],  Br[(d*NSTATE+n)*2+1]);
        float2 Cc = make_float2(Ctr[(d*NSTATE+n)*2], -Ctr[(d*NSTATE+n)*2+1]);
        w00[n] = cmulf(Cc, Bv);
        w01[n] = cmulf(Cc, p);
        w10[n] = cmulf(qc, Bv);
        w11[n] = cmulf(qc, p);
        lams[n] = lm;
    }
    if (tid == 0) s_inv2step = 2.0f * expf(-logstep[d]);
    __syncthreads();

    float inv2step = s_inv2step;
    {
        float2 a00[4], a01[4], a10[4], a11[4];
        float  gims[4], ts[4];
#pragma unroll
        for (int k = 0; k < 4; k++) {
            int l = tid + k * 512;
            float theta = (PI_F / (float)LSEQ) * (float)l;
            float t = tanf(theta);
            ts[k] = t;
            gims[k] = -inv2step * t;
            a00[k] = make_float2(0.f, 0.f);
            a01[k] = make_float2(0.f, 0.f);
            a10[k] = make_float2(0.f, 0.f);
            a11[k] = make_float2(0.f, 0.f);
        }
        for (int n = 0; n < NSTATE; n++) {
            float2 lw = lams[n];
            float2 v00 = w00[n], v01 = w01[n], v10 = w10[n], v11 = w11[n];
            float dr = -lw.x;
#pragma unroll
            for (int k = 0; k < 4; k++) {
                float di  = gims[k] - lw.y;
                float inv = __fdividef(1.0f, dr * dr + di * di);
                float rx = dr * inv, ry = -di * inv;
                a00[k].x += v00.x * rx - v00.y * ry;  a00[k].y += v00.x * ry + v00.y * rx;
                a01[k].x += v01.x * rx - v01.y * ry;  a01[k].y += v01.x * ry + v01.y * rx;
                a10[k].x += v10.x * rx - v10.y * ry;  a10[k].y += v10.x * ry + v10.y * rx;
                a11[k].x += v11.x * rx - v11.y * ry;  a11[k].y += v11.x * ry + v11.y * rx;
            }
        }
#pragma unroll
        for (int k = 0; k < 4; k++) {
            int l = tid + k * 512;
            float2 den = make_float2(1.0f + a11[k].x, a11[k].y);
            float dinv = __fdividef(1.0f, den.x * den.x + den.y * den.y);
            float2 num = cmulf(a01[k], a10[k]);
            float2 frac = make_float2((num.x * den.x + num.y * den.y) * dinv,
                                      (num.y * den.x - num.x * den.y) * dinv);
            float2 inner = make_float2(a00[k].x - frac.x, a00[k].y - frac.y);
            float2 c = make_float2(1.0f, -ts[k]);
            buf0[SWZ(l)] = cmulf(c, inner);
        }
    }
    __syncthreads();

    float2* res = ifft2048_mr(buf0, buf1, tid, 512);
    float2* oth = (res == buf0) ? buf1 : buf0;

    const float invL = 1.0f / (float)LSEQ;
    for (int m = tid; m < LSEQ; m += 512) {
        float kr = res[SWZ((LSEQ - m) & (LSEQ - 1))].x * invL;
        oth[SWZ(m)]        = make_float2(kr, 0.0f);
        oth[SWZ(m + LSEQ)] = make_float2(0.0f, 0.0f);
    }
    __syncthreads();

    float2* res2 = fft4096_r8<true>(oth, res, tid, 512);
    const float invF = 1.0f / (float)LFFT;
    for (int k = tid; k < LFFT; k += 512) {
        float2 v = res2[SWZ(k)];
        g_Khat[d * LFFT + k] = make_float2(v.x * invF, v.y * invF);
    }
}

// ---------------------------------------------------------------------------
// conv kernel: 256 threads, thread owns j-pair (2t, 2t+1). float4 smem.
// fwd FFT (4 stages) -> fused pointwise + inverse stage 0 -> 2 stages ->
// final stage streamed straight to global with the D*u add.
// ---------------------------------------------------------------------------
__global__ void __launch_bounds__(256, 2) conv_kernel(
    const float* __restrict__ u, const float* __restrict__ Dvec,
    float* __restrict__ out) {
    extern __shared__ float4 smf4[];   // [2][2048]

    int t    = threadIdx.x;
    int blk  = blockIdx.x;
    int pair = blk & (DMODEL / 2 - 1);
    int b    = blk >> 8;
    int d0   = pair * 2;
    int tS   = SW4(t);

    const float2* uf2 = reinterpret_cast<const float2*>(u);
    const size_t ubase = (size_t)b * (size_t)(LSEQ * (DMODEL / 2)) + (size_t)pair;

    // load u into smem (packed pair complex) + keep for the D*u epilogue
    float2 ua[4], ub[4];
#pragma unroll
    for (int r = 0; r < 4; r++) {
        int l = 2 * t + 512 * r;
        ua[r] = uf2[ubase + (size_t)l * (DMODEL / 2)];
        ub[r] = uf2[ubase + (size_t)(l + 1) * (DMODEL / 2)];
        smf4[tS + 256 * r] = make_float4(ua[r].x, ua[r].y, ub[r].x, ub[r].y);
    }
#pragma unroll
    for (int r = 4; r < 8; r++)
        smf4[tS + 256 * r] = make_float4(0.f, 0.f, 0.f, 0.f);
    __syncthreads();

    // forward FFT: cur 0->1->0->1->0
    conv_stage<1,   false>(smf4, 0, t, tS);
    conv_stage<8,   false>(smf4, 1, t, tS);
    conv_stage<64,  false>(smf4, 0, t, tS);
    conv_stage<512, false>(smf4, 1, t, tS);

    // inverse stage 0 fused with pointwise spectrum multiply (reads buf 0)
    const float4* K0 = reinterpret_cast<const float4*>(g_Khat + (size_t)d0 * LFFT);
    const float4* K1 = K0 + (LFFT / 2);
    inv_stage0_pw(smf4, 0, t, tS, K0, K1);

    conv_stage<8,  true>(smf4, 1, t, tS);
    conv_stage<64, true>(smf4, 0, t, tS);

    // final inverse stage (Ns=512), streamed to global; r>=4 are times >= L -> discard
    {
        const float4* src = smf4 + 1 * 2048;
        float2 v0[8], v1[8];
#pragma unroll
        for (int r = 0; r < 8; r++) {
            float4 z = src[tS + 256 * r];
            v0[r] = make_float2(z.x, z.y);
            v1[r] = make_float2(z.z, z.w);
        }
        float4 W1a = g_twd[2048 + 2*t], W2a = g_twd[1024 + 2*t], W4a = g_twd[512 + 2*t];
        float4 W1b = g_twd[2049 + 2*t], W2b = g_twd[1025 + 2*t], W4b = g_twd[513 + 2*t];
        twapply8<true>(v0, W1a, W2a, W4a);
        twapply8<true>(v1, W1b, W2b, W4b);
        fft8<false>(v0); fft8<false>(v1);

        float D0 = Dvec[d0], D1 = Dvec[d0 + 1];
        float2* of2 = reinterpret_cast<float2*>(out);
#pragma unroll
        for (int r = 0; r < 4; r++) {
            int l0 = 2 * t + 512 * r;
            of2[ubase + (size_t)l0 * (DMODEL / 2)] =
                make_float2(v0[r].x + D0 * ua[r].x, v0[r].y + D1 * ua[r].y);
            of2[ubase + (size_t)(l0 + 1) * (DMODEL / 2)] =
                make_float2(v1[r].x + D0 * ub[r].x, v1[r].y + D1 * ub[r].y);
        }
    }
}

// ---------------------------------------------------------------------------
// Inputs: u, p_ri, q_ri, lam_ri, B_ri, Ct_ri, D, log_step
// ---------------------------------------------------------------------------
extern "C" void kernel_launch(void* const* d_in, const int* in_sizes, int n_in,
                              void* d_out, int out_size) {
    const float* u   = (const float*)d_in[0];
    const float* pr  = (const float*)d_in[1];
    const float* qr  = (const float*)d_in[2];
    const float* lam = (const float*)d_in[3];
    const float* Br  = (const float*)d_in[4];
    const float* Ct  = (const float*)d_in[5];
    const float* Dv  = (const float*)d_in[6];
    const float* ls  = (const float*)d_in[7];
    float* out = (float*)d_out;

    const int smem_khat = 2 * LFFT * (int)sizeof(float2);   // 64 KB
    const int smem_conv = 2 * 2048 * (int)sizeof(float4);   // 64 KB
    cudaFuncSetAttribute(khat_kernel, cudaFuncAttributeMaxDynamicSharedMemorySize, smem_khat);
    cudaFuncSetAttribute(conv_kernel, cudaFuncAttributeMaxDynamicSharedMemorySize, smem_conv);

    init_twd_kernel<<<LFFT / 512, 512>>>();
    khat_kernel<<<DMODEL, 512, smem_khat>>>(pr, qr, lam, Br, Ct, ls);
    // pads so ncu's skip-5 capture lands on conv_kernel (launch #6)
    pad_kernel<<<1, 32>>>();
    pad_kernel<<<1, 32>>>();
    pad_kernel<<<1, 32>>>();
    conv_kernel<<<NBATCH * (DMODEL / 2), 256, smem_conv>>>(u, Dv, out);
}

// round 4
// speedup vs baseline: 1.9012x; 1.1645x over previous
#include <cuda_runtime.h>
#include <math.h>

#define LSEQ   2048
#define LFFT   4096
#define DMODEL 512
#define NSTATE 64
#define NBATCH 16
#define NPAIR  (DMODEL / 2)
#define PI_F   3.14159265358979323846f

#define SWZ(i) ((i) ^ (((i) >> 3) & 15))   // float2-granularity (khat)
#define SW4(e) ((e) ^ (((e) >> 3) & 7))    // float4-granularity (conv)

__device__ float4 g_Khat4[DMODEL * LFFT / 2];          // Khat (1/LFFT folded in)
__device__ float4 g_twd[LFFT];                          // (c,s,-s,c): e^{-i pi base/Ns}
__device__ float4 g_ut[NBATCH * NPAIR * (LSEQ / 2)];    // 64MB transposed input
__device__ float4 g_yt[NBATCH * NPAIR * (LSEQ / 2)];    // 64MB transposed output

__device__ __forceinline__ float2 cmulf(float2 a, float2 b) {
    return make_float2(a.x * b.x - a.y * b.y, a.x * b.y + a.y * b.x);
}
__device__ __forceinline__ float2 cadd(float2 a, float2 b) { return make_float2(a.x + b.x, a.y + b.y); }
__device__ __forceinline__ float2 csub(float2 a, float2 b) { return make_float2(a.x - b.x, a.y - b.y); }
__device__ __forceinline__ float2 cmulF(float2 v, float2 wn, float2 wr) {
    return make_float2(v.x * wn.x + v.y * wr.x, v.x * wn.y + v.y * wr.y);
}

template<bool FWD> __device__ __forceinline__ float2 mul_j(float2 a) {
    return FWD ? make_float2(a.y, -a.x) : make_float2(-a.y, a.x);
}
template<bool FWD> __device__ __forceinline__ float2 mul_w1(float2 a) {
    const float C = 0.70710678118654752f;
    return FWD ? make_float2(C * (a.x + a.y), C * (a.y - a.x))
               : make_float2(C * (a.x - a.y), C * (a.x + a.y));
}
template<bool FWD> __device__ __forceinline__ float2 mul_w3(float2 a) {
    const float C = 0.70710678118654752f;
    return FWD ? make_float2(C * (a.y - a.x), -C * (a.x + a.y))
               : make_float2(-C * (a.x + a.y), C * (a.x - a.y));
}

template<bool FWD>
__device__ __forceinline__ void fft8(float2* v) {
    float2 t0 = cadd(v[0], v[4]), t4 = csub(v[0], v[4]);
    float2 t1 = cadd(v[1], v[5]), t5 = mul_w1<FWD>(csub(v[1], v[5]));
    float2 t2 = cadd(v[2], v[6]), t6 = mul_j<FWD>(csub(v[2], v[6]));
    float2 t3 = cadd(v[3], v[7]), t7 = mul_w3<FWD>(csub(v[3], v[7]));
    float2 u0 = cadd(t0, t2), u2 = csub(t0, t2);
    float2 u1 = cadd(t1, t3), u3 = mul_j<FWD>(csub(t1, t3));
    float2 u4 = cadd(t4, t6), u6 = csub(t4, t6);
    float2 u5 = cadd(t5, t7), u7 = mul_j<FWD>(csub(t5, t7));
    v[0] = cadd(u0, u1); v[4] = csub(u0, u1);
    v[2] = cadd(u2, u3); v[6] = csub(u2, u3);
    v[1] = cadd(u4, u5); v[5] = csub(u4, u5);
    v[3] = cadd(u6, u7); v[7] = csub(u6, u7);
}

// forward fft8 with inputs v[4..7] == 0 (zero-padded top half)
__device__ __forceinline__ void fft8_z4(const float2* a, float2* v) {
    float2 t0 = a[0], t4 = a[0];
    float2 t1 = a[1], t5 = mul_w1<true>(a[1]);
    float2 t2 = a[2], t6 = mul_j<true>(a[2]);
    float2 t3 = a[3], t7 = mul_w3<true>(a[3]);
    float2 u0 = cadd(t0, t2), u2 = csub(t0, t2);
    float2 u1 = cadd(t1, t3), u3 = mul_j<true>(csub(t1, t3));
    float2 u4 = cadd(t4, t6), u6 = csub(t4, t6);
    float2 u5 = cadd(t5, t7), u7 = mul_j<true>(csub(t5, t7));
    v[0] = cadd(u0, u1); v[4] = csub(u0, u1);
    v[2] = cadd(u2, u3); v[6] = csub(u2, u3);
    v[1] = cadd(u4, u5); v[5] = csub(u4, u5);
    v[3] = cadd(u6, u7); v[7] = csub(u6, u7);
}

// inverse fft8, only bins 0..3 produced (others discarded by zero-trim)
__device__ __forceinline__ void fft8_lo4(const float2* v, float2* o) {
    float2 t0 = cadd(v[0], v[4]), t4 = csub(v[0], v[4]);
    float2 t1 = cadd(v[1], v[5]), t5 = mul_w1<false>(csub(v[1], v[5]));
    float2 t2 = cadd(v[2], v[6]), t6 = mul_j<false>(csub(v[2], v[6]));
    float2 t3 = cadd(v[3], v[7]), t7 = mul_w3<false>(csub(v[3], v[7]));
    float2 u0 = cadd(t0, t2);
    float2 u1 = cadd(t1, t3);
    float2 u2 = csub(t0, t2);
    float2 u3 = mul_j<false>(csub(t1, t3));
    float2 u4 = cadd(t4, t6);
    float2 u5 = cadd(t5, t7);
    float2 u6 = csub(t4, t6);
    float2 u7 = mul_j<false>(csub(t5, t7));
    o[0] = cadd(u0, u1); o[1] = cadd(u4, u5);
    o[2] = cadd(u2, u3); o[3] = cadd(u6, u7);
}

template<bool FWD>
__device__ __forceinline__ void fft4(float2* v) {
    float2 t0 = cadd(v[0], v[2]), t2 = csub(v[0], v[2]);
    float2 t1 = cadd(v[1], v[3]), t3 = mul_j<FWD>(csub(v[1], v[3]));
    v[0] = cadd(t0, t1); v[2] = csub(t0, t1);
    v[1] = cadd(t2, t3); v[3] = csub(t2, t3);
}

template<bool INV>
__device__ __forceinline__ void twapply8(float2* v, float4 W1, float4 W2, float4 W4) {
    float2 w1n, w1r, w2n, w2r, w4n, w4r;
    if (!INV) {
        w1n = make_float2(W1.x, W1.y); w1r = make_float2(W1.z, W1.w);
        w2n = make_float2(W2.x, W2.y); w2r = make_float2(W2.z, W2.w);
        w4n = make_float2(W4.x, W4.y); w4r = make_float2(W4.z, W4.w);
    } else {
        w1n = make_float2(W1.x, -W1.y); w1r = make_float2(-W1.z, W1.w);
        w2n = make_float2(W2.x, -W2.y); w2r = make_float2(-W2.z, W2.w);
        w4n = make_float2(W4.x, -W4.y); w4r = make_float2(-W4.z, W4.w);
    }
    float2 w3n = cmulF(w2n, w1n, w1r); float2 w3r = make_float2(-w3n.y, w3n.x);
    float2 w5n = cmulF(w4n, w1n, w1r); float2 w5r = make_float2(-w5n.y, w5n.x);
    float2 w6n = cmulF(w4n, w2n, w2r); float2 w6r = make_float2(-w6n.y, w6n.x);
    float2 w7n = cmulF(w4n, w3n, w3r); float2 w7r = make_float2(-w7n.y, w7n.x);
    v[1] = cmulF(v[1], w1n, w1r); v[2] = cmulF(v[2], w2n, w2r); v[3] = cmulF(v[3], w3n, w3r);
    v[4] = cmulF(v[4], w4n, w4r); v[5] = cmulF(v[5], w5n, w5r); v[6] = cmulF(v[6], w6n, w6r);
    v[7] = cmulF(v[7], w7n, w7r);
}

// ---------------------------------------------------------------------------
// One in-place radix-8 stage on the single 2048-float4 smem buffer.
// Read all -> sync -> write all -> sync. Thread owns j-pair (2t, 2t+1).
// ---------------------------------------------------------------------------
template<int NS, bool INV>
__device__ __forceinline__ void stage_ip(float4* s, int t, int tS) {
    float2 v0[8], v1[8];
#pragma unroll
    for (int r = 0; r < 8; r++) {
        float4 z = s[tS + 256 * r];
        v0[r] = make_float2(z.x, z.y);
        v1[r] = make_float2(z.z, z.w);
    }
    int base0 = (2 * t) & (NS - 1);
    {
        float4 W1a = g_twd[4 * NS + base0],     W2a = g_twd[2 * NS + base0],     W4a = g_twd[NS + base0];
        float4 W1b = g_twd[4 * NS + base0 + 1], W2b = g_twd[2 * NS + base0 + 1], W4b = g_twd[NS + base0 + 1];
        twapply8<INV>(v0, W1a, W2a, W4a);
        twapply8<INV>(v1, W1b, W2b, W4b);
    }
    fft8<!INV>(v0); fft8<!INV>(v1);
    __syncthreads();
    int eBase = ((2 * t - base0) << 2) + (base0 >> 1);
#pragma unroll
    for (int r = 0; r < 8; r++)
        s[SW4(eBase + (NS >> 1) * r)] = make_float4(v0[r].x, v0[r].y, v1[r].x, v1[r].y);
    __syncthreads();
}

__device__ __forceinline__ float2 pwone(float2 z, float2 zm, float2 K0k, float2 K1k) {
    float2 u0  = make_float2(0.5f * (z.x + zm.x), 0.5f * (z.y - zm.y));
    float2 iu1 = make_float2(0.5f * (z.x - zm.x), 0.5f * (z.y + zm.y));
    float2 u1  = make_float2(iu1.y, -iu1.x);
    float2 y0 = cmulf(u0, K0k);
    float2 y1 = cmulf(u1, K1k);
    return make_float2(y0.x - y1.y, y0.y + y1.x);
}

// inverse stage 0 (Ns=1) fused with spectrum split + multiply, in-place
__device__ __forceinline__ void inv_stage0_pw_ip(float4* s, int t, int tS,
                                                 const float4* K0, const float4* K1) {
    const float2* sF2 = reinterpret_cast<const float2*>(s);
    float2 v0[8], v1[8];
    int sA0 = SW4(2048 - t);   // mirror for k=2e (slot 0); e==0 special-cased
    int sB0 = SW4(2047 - t);   // mirror for k=2e+1 (slot 1)
#pragma unroll
    for (int r = 0; r < 8; r++) {
        float4 z4 = s[tS + 256 * r];
        float2 z1 = make_float2(z4.x, z4.y);
        float2 z2 = make_float2(z4.z, z4.w);
        int e = t + 256 * r;
        float2 zm1 = (e == 0) ? z1 : sF2[(sA0 - 256 * r) * 2];
        float2 zm2 = sF2[(sB0 - 256 * r) * 2 + 1];
        float4 k0 = K0[e];
        float4 k1 = K1[e];
        v0[r] = pwone(z1, zm1, make_float2(k0.x, k0.y), make_float2(k1.x, k1.y));
        v1[r] = pwone(z2, zm2, make_float2(k0.z, k0.w), make_float2(k1.z, k1.w));
    }
    fft8<false>(v0); fft8<false>(v1);
    __syncthreads();
#pragma unroll
    for (int m = 0; m < 4; m++) {
        s[SW4(8 * t + m)]     = make_float4(v0[2*m].x, v0[2*m].y, v0[2*m+1].x, v0[2*m+1].y);
        s[SW4(8 * t + 4 + m)] = make_float4(v1[2*m].x, v1[2*m].y, v1[2*m+1].x, v1[2*m+1].y);
    }
    __syncthreads();
}

__global__ void init_twd_kernel() {
    int i = blockIdx.x * blockDim.x + threadIdx.x;
    if (i >= LFFT) return;
    if (i == 0) { g_twd[0] = make_float4(1.0f, 0.0f, 0.0f, 1.0f); return; }
    int k = 31 - __clz(i);
    int Ns = 1 << k;
    int base = i - Ns;
    float ang = -PI_F * (float)base / (float)Ns;
    float s, c;
    sincosf(ang, &s, &c);
    g_twd[i] = make_float4(c, s, -s, c);
}

// ---------------------------------------------------------------------------
// T1: u[B,L,D] f32 -> g_ut[b][pair][l] float2, coalesced both sides.
// ---------------------------------------------------------------------------
__global__ void __launch_bounds__(256) t1_kernel(const float* __restrict__ u) {
    __shared__ float2 tile[32][33];
    int pt = blockIdx.x * 32;            // pair tile
    int rt = blockIdx.y * 32;            // row tile, row = b*LSEQ + l
    int tx = threadIdx.x & 31, ty = threadIdx.x >> 5;
    const float2* uf2 = reinterpret_cast<const float2*>(u);
#pragma unroll
    for (int i = 0; i < 4; i++) {
        int row = ty + i * 8;
        tile[row][tx] = uf2[(size_t)(rt + row) * NPAIR + pt + tx];
    }
    __syncthreads();
    int b = rt >> 11, l0 = rt & (LSEQ - 1);
    float2* ut2 = reinterpret_cast<float2*>(g_ut);
#pragma unroll
    for (int i = 0; i < 4; i++) {
        int p = pt + ty + i * 8;
        ut2[((size_t)(b * NPAIR + p)) * LSEQ + l0 + tx] = tile[tx][ty + i * 8];
    }
}

// T2: g_yt[b][pair][l] float2 -> out[B,L,D]
__global__ void __launch_bounds__(256) t2_kernel(float* __restrict__ out) {
    __shared__ float2 tile[32][33];
    int pt = blockIdx.x * 32;
    int rt = blockIdx.y * 32;
    int tx = threadIdx.x & 31, ty = threadIdx.x >> 5;
    int b = rt >> 11, l0 = rt & (LSEQ - 1);
    const float2* yt2 = reinterpret_cast<const float2*>(g_yt);
#pragma unroll
    for (int i = 0; i < 4; i++) {
        int p = pt + ty + i * 8;
        tile[ty + i * 8][tx] = yt2[((size_t)(b * NPAIR + p)) * LSEQ + l0 + tx];
    }
    __syncthreads();
    float2* of2 = reinterpret_cast<float2*>(out);
#pragma unroll
    for (int i = 0; i < 4; i++) {
        int row = ty + i * 8;
        of2[(size_t)(rt + row) * NPAIR + pt + tx] = tile[tx][row];
    }
}

// ---------------------------------------------------------------------------
// khat (unchanged from R3): Cauchy -> ifft2048 -> pad -> fft4096 -> Khat
// ---------------------------------------------------------------------------
template<bool FWD>
__device__ float2* fft4096_r8(float2* src, float2* dst, int tid, int nth) {
#pragma unroll
    for (int s = 0; s < 4; s++) {
        const int Ns = 1 << (3 * s);
        for (int j = tid; j < 512; j += nth) {
            float2 v[8];
#pragma unroll
            for (int r = 0; r < 8; r++) v[r] = src[SWZ(j + r * 512)];
            const int base = j & (Ns - 1);
            if (Ns > 1) {
                float4 T1 = g_twd[4 * Ns + base];
                float4 T2 = g_twd[2 * Ns + base];
                float4 T4 = g_twd[Ns + base];
                float2 w1 = make_float2(T1.x, FWD ? T1.y : -T1.y);
                float2 w2 = make_float2(T2.x, FWD ? T2.y : -T2.y);
                float2 w4 = make_float2(T4.x, FWD ? T4.y : -T4.y);
                float2 w3 = cmulf(w1, w2), w5 = cmulf(w1, w4);
                float2 w6 = cmulf(w2, w4), w7 = cmulf(w3, w4);
                v[1] = cmulf(v[1], w1); v[2] = cmulf(v[2], w2); v[3] = cmulf(v[3], w3);
                v[4] = cmulf(v[4], w4); v[5] = cmulf(v[5], w5); v[6] = cmulf(v[6], w6);
                v[7] = cmulf(v[7], w7);
            }
            fft8<FWD>(v);
            const int idxD = ((j - base) << 3) + base;
#pragma unroll
            for (int r = 0; r < 8; r++) dst[SWZ(idxD + r * Ns)] = v[r];
        }
        __syncthreads();
        float2* t = src; src = dst; dst = t;
    }
    return src;
}

__device__ float2* ifft2048_mr(float2* src, float2* dst, int tid, int nth) {
#pragma unroll
    for (int s = 0; s < 3; s++) {
        const int Ns = 1 << (3 * s);
        for (int j = tid; j < 256; j += nth) {
            float2 v[8];
#pragma unroll
            for (int r = 0; r < 8; r++) v[r] = src[SWZ(j + r * 256)];
            const int base = j & (Ns - 1);
            if (Ns > 1) {
                float4 T1 = g_twd[4 * Ns + base];
                float4 T2 = g_twd[2 * Ns + base];
                float4 T4 = g_twd[Ns + base];
                float2 w1 = make_float2(T1.x, -T1.y);
                float2 w2 = make_float2(T2.x, -T2.y);
                float2 w4 = make_float2(T4.x, -T4.y);
                float2 w3 = cmulf(w1, w2), w5 = cmulf(w1, w4);
                float2 w6 = cmulf(w2, w4), w7 = cmulf(w3, w4);
                v[1] = cmulf(v[1], w1); v[2] = cmulf(v[2], w2); v[3] = cmulf(v[3], w3);
                v[4] = cmulf(v[4], w4); v[5] = cmulf(v[5], w5); v[6] = cmulf(v[6], w6);
                v[7] = cmulf(v[7], w7);
            }
            fft8<false>(v);
            const int idxD = ((j - base) << 3) + base;
#pragma unroll
            for (int r = 0; r < 8; r++) dst[SWZ(idxD + r * Ns)] = v[r];
        }
        __syncthreads();
        float2* t = src; src = dst; dst = t;
    }
    for (int j = tid; j < 512; j += nth) {
        float2 v[4];
#pragma unroll
        for (int r = 0; r < 4; r++) v[r] = src[SWZ(j + r * 512)];
        float4 T1 = g_twd[1024 + j];
        float4 T2 = g_twd[512 + j];
        float2 w1 = make_float2(T1.x, -T1.y);
        float2 w2 = make_float2(T2.x, -T2.y);
        float2 w3 = cmulf(w1, w2);
        v[1] = cmulf(v[1], w1); v[2] = cmulf(v[2], w2); v[3] = cmulf(v[3], w3);
        fft4<false>(v);
#pragma unroll
        for (int r = 0; r < 4; r++) dst[SWZ(j + r * 512)] = v[r];
    }
    __syncthreads();
    return dst;
}

__global__ void __launch_bounds__(512, 2) khat_kernel(
    const float* __restrict__ pr, const float* __restrict__ qr,
    const float* __restrict__ lamr, const float* __restrict__ Br,
    const float* __restrict__ Ctr, const float* __restrict__ logstep) {
    extern __shared__ float2 sm[];
    float2* buf0 = sm;
    float2* buf1 = sm + LFFT;

    __shared__ float2 w00[NSTATE], w01[NSTATE], w10[NSTATE], w11[NSTATE];
    __shared__ float2 lams[NSTATE];
    __shared__ float s_inv2step;

    int d = blockIdx.x;
    int tid = threadIdx.x;

    if (tid < NSTATE) {
        int n = tid;
        float2 p  = make_float2(pr[2*n],  pr[2*n+1]);
        float2 qc = make_float2(qr[2*n], -qr[2*n+1]);
        float2 lm = make_float2(lamr[2*n], lamr[2*n+1]);
        float2 Bv = make_float2(Br[(d*NSTATE+n)*2],  Br[(d*NSTATE+n)*2+1]);
        float2 Cc = make_float2(Ctr[(d*NSTATE+n)*2], -Ctr[(d*NSTATE+n)*2+1]);
        w00[n] = cmulf(Cc, Bv);
        w01[n] = cmulf(Cc, p);
        w10[n] = cmulf(qc, Bv);
        w11[n] = cmulf(qc, p);
        lams[n] = lm;
    }
    if (tid == 0) s_inv2step = 2.0f * expf(-logstep[d]);
    __syncthreads();

    float inv2step = s_inv2step;
    {
        float2 a00[4], a01[4], a10[4], a11[4];
        float  gims[4], ts[4];
#pragma unroll
        for (int k = 0; k < 4; k++) {
            int l = tid + k * 512;
            float theta = (PI_F / (float)LSEQ) * (float)l;
            float t = tanf(theta);
            ts[k] = t;
            gims[k] = -inv2step * t;
            a00[k] = make_float2(0.f, 0.f);
            a01[k] = make_float2(0.f, 0.f);
            a10[k] = make_float2(0.f, 0.f);
            a11[k] = make_float2(0.f, 0.f);
        }
        for (int n = 0; n < NSTATE; n++) {
            float2 lw = lams[n];
            float2 v00 = w00[n], v01 = w01[n], v10 = w10[n], v11 = w11[n];
            float dr = -lw.x;
#pragma unroll
            for (int k = 0; k < 4; k++) {
                float di  = gims[k] - lw.y;
                float inv = __fdividef(1.0f, dr * dr + di * di);
                float rx = dr * inv, ry = -di * inv;
                a00[k].x += v00.x * rx - v00.y * ry;  a00[k].y += v00.x * ry + v00.y * rx;
                a01[k].x += v01.x * rx - v01.y * ry;  a01[k].y += v01.x * ry + v01.y * rx;
                a10[k].x += v10.x * rx - v10.y * ry;  a10[k].y += v10.x * ry + v10.y * rx;
                a11[k].x += v11.x * rx - v11.y * ry;  a11[k].y += v11.x * ry + v11.y * rx;
            }
        }
#pragma unroll
        for (int k = 0; k < 4; k++) {
            int l = tid + k * 512;
            float2 den = make_float2(1.0f + a11[k].x, a11[k].y);
            float dinv = __fdividef(1.0f, den.x * den.x + den.y * den.y);
            float2 num = cmulf(a01[k], a10[k]);
            float2 frac = make_float2((num.x * den.x + num.y * den.y) * dinv,
                                      (num.y * den.x - num.x * den.y) * dinv);
            float2 inner = make_float2(a00[k].x - frac.x, a00[k].y - frac.y);
            float2 c = make_float2(1.0f, -ts[k]);
            buf0[SWZ(l)] = cmulf(c, inner);
        }
    }
    __syncthreads();

    float2* res = ifft2048_mr(buf0, buf1, tid, 512);
    float2* oth = (res == buf0) ? buf1 : buf0;

    const float invL = 1.0f / (float)LSEQ;
    for (int m = tid; m < LSEQ; m += 512) {
        float kr = res[SWZ((LSEQ - m) & (LSEQ - 1))].x * invL;
        oth[SWZ(m)]        = make_float2(kr, 0.0f);
        oth[SWZ(m + LSEQ)] = make_float2(0.0f, 0.0f);
    }
    __syncthreads();

    float2* res2 = fft4096_r8<true>(oth, res, tid, 512);
    const float invF = 1.0f / (float)LFFT;
    float2* KH = reinterpret_cast<float2*>(g_Khat4);
    for (int k = tid; k < LFFT; k += 512) {
        float2 v = res2[SWZ(k)];
        KH[d * LFFT + k] = make_float2(v.x * invF, v.y * invF);
    }
}

// ---------------------------------------------------------------------------
// conv kernel: 32KB single smem buffer, in-place stages, 2 CTAs/SM.
// Coalesced I/O via g_ut / g_yt. Stage-0 fused with load (zero-padded half),
// final inverse stage streams to g_yt with D*u add.
// ---------------------------------------------------------------------------
__global__ void __launch_bounds__(256, 2) conv_kernel(const float* __restrict__ Dvec) {
    extern __shared__ float4 s[];   // 2048 float4 = 32KB

    int t    = threadIdx.x;
    int blk  = blockIdx.x;
    int pair = blk & (NPAIR - 1);
    int b    = blk >> 8;
    int d0   = pair * 2;
    int tS   = SW4(t);

    const float4* ut = g_ut + ((size_t)(b * NPAIR + pair)) * (LSEQ / 2);
    float4*       yt = g_yt + ((size_t)(b * NPAIR + pair)) * (LSEQ / 2);

    // load + forward stage 0 (Ns=1) entirely in registers (top half zero)
    float4 uin[4];
    {
        float2 a[4], bb[4], v0[8], v1[8];
#pragma unroll
        for (int r = 0; r < 4; r++) {
            uin[r] = ut[t + 256 * r];
            a[r]  = make_float2(uin[r].x, uin[r].y);
            bb[r] = make_float2(uin[r].z, uin[r].w);
        }
        fft8_z4(a, v0);
        fft8_z4(bb, v1);
#pragma unroll
        for (int m = 0; m < 4; m++) {
            s[SW4(8 * t + m)]     = make_float4(v0[2*m].x, v0[2*m].y, v0[2*m+1].x, v0[2*m+1].y);
            s[SW4(8 * t + 4 + m)] = make_float4(v1[2*m].x, v1[2*m].y, v1[2*m+1].x, v1[2*m+1].y);
        }
        __syncthreads();
    }

    stage_ip<8,   false>(s, t, tS);
    stage_ip<64,  false>(s, t, tS);
    stage_ip<512, false>(s, t, tS);

    const float4* K0 = g_Khat4 + (size_t)d0 * (LFFT / 2);
    const float4* K1 = K0 + (LFFT / 2);
    inv_stage0_pw_ip(s, t, tS, K0, K1);

    stage_ip<8,  true>(s, t, tS);
    stage_ip<64, true>(s, t, tS);

    // final inverse stage (Ns=512): read smem, keep only output bins 0..3,
    // stream to g_yt with the D*u residual add.
    {
        float2 v0[8], v1[8], o0[4], o1[4];
#pragma unroll
        for (int r = 0; r < 8; r++) {
            float4 z = s[tS + 256 * r];
            v0[r] = make_float2(z.x, z.y);
            v1[r] = make_float2(z.z, z.w);
        }
        float4 W1a = g_twd[2048 + 2*t], W2a = g_twd[1024 + 2*t], W4a = g_twd[512 + 2*t];
        float4 W1b = g_twd[2049 + 2*t], W2b = g_twd[1025 + 2*t], W4b = g_twd[513 + 2*t];
        twapply8<true>(v0, W1a, W2a, W4a);
        twapply8<true>(v1, W1b, W2b, W4b);
        fft8_lo4(v0, o0);
        fft8_lo4(v1, o1);

        float D0 = Dvec[d0], D1 = Dvec[d0 + 1];
#pragma unroll
        for (int r = 0; r < 4; r++) {
            yt[t + 256 * r] = make_float4(
                o0[r].x + D0 * uin[r].x, o0[r].y + D1 * uin[r].y,
                o1[r].x + D0 * uin[r].z, o1[r].y + D1 * uin[r].w);
        }
    }
}

// ---------------------------------------------------------------------------
// Inputs: u, p_ri, q_ri, lam_ri, B_ri, Ct_ri, D, log_step
// Launch order puts conv at launch index 3 (ncu -s 5 alignment).
// ---------------------------------------------------------------------------
extern "C" void kernel_launch(void* const* d_in, const int* in_sizes, int n_in,
                              void* d_out, int out_size) {
    const float* u   = (const float*)d_in[0];
    const float* pr  = (const float*)d_in[1];
    const float* qr  = (const float*)d_in[2];
    const float* lam = (const float*)d_in[3];
    const float* Br  = (const float*)d_in[4];
    const float* Ct  = (const float*)d_in[5];
    const float* Dv  = (const float*)d_in[6];
    const float* ls  = (const float*)d_in[7];
    float* out = (float*)d_out;

    const int smem_khat = 2 * LFFT * (int)sizeof(float2);   // 64 KB
    const int smem_conv = 2048 * (int)sizeof(float4);       // 32 KB
    cudaFuncSetAttribute(khat_kernel, cudaFuncAttributeMaxDynamicSharedMemorySize, smem_khat);
    cudaFuncSetAttribute(conv_kernel, cudaFuncAttributeMaxDynamicSharedMemorySize, smem_conv);

    t1_kernel<<<dim3(NPAIR / 32, NBATCH * LSEQ / 32), 256>>>(u);            // 0
    init_twd_kernel<<<LFFT / 512, 512>>>();                                  // 1
    khat_kernel<<<DMODEL, 512, smem_khat>>>(pr, qr, lam, Br, Ct, ls);        // 2
    conv_kernel<<<NBATCH * NPAIR, 256, smem_conv>>>(Dv);                     // 3  <- ncu target
    t2_kernel<<<dim3(NPAIR / 32, NBATCH * LSEQ / 32), 256>>>(out);           // 4
}

// round 5
// speedup vs baseline: 2.0591x; 1.0831x over previous
#include <cuda_runtime.h>
#include <math.h>

#define LSEQ   2048
#define LFFT   4096
#define DMODEL 512
#define NSTATE 64
#define NBATCH 16
#define NPAIR  (DMODEL / 2)
#define PI_F   3.14159265358979323846f

#define SWZ(i) ((i) ^ (((i) >> 3) & 15))   // float2-granularity (khat)
#define SW4(e) ((e) ^ (((e) >> 3) & 7))    // float4-granularity (conv)

typedef unsigned long long ull;

__device__ float4 g_Khat4[DMODEL * LFFT / 2];
__device__ float4 g_twd[LFFT];                          // (c,s,-s,c): e^{-i pi base/Ns}
__device__ float4 g_ut[NBATCH * NPAIR * (LSEQ / 2)];
__device__ float4 g_yt[NBATCH * NPAIR * (LSEQ / 2)];

// ---------------- packed f32x2 helpers (Blackwell FFMA2 path) ----------------
__device__ __forceinline__ ull pk(float x, float y) {
    ull r; asm("mov.b64 %0, {%1,%2};" : "=l"(r) : "f"(x), "f"(y)); return r;
}
__device__ __forceinline__ void upk(ull v, float& x, float& y) {
    asm("mov.b64 {%0,%1}, %2;" : "=f"(x), "=f"(y) : "l"(v));
}
__device__ __forceinline__ ull padd(ull a, ull b) {
    ull r; asm("add.rn.f32x2 %0, %1, %2;" : "=l"(r) : "l"(a), "l"(b)); return r;
}
__device__ __forceinline__ ull pmul(ull a, ull b) {
    ull r; asm("mul.rn.f32x2 %0, %1, %2;" : "=l"(r) : "l"(a), "l"(b)); return r;
}
__device__ __forceinline__ ull pfma(ull a, ull b, ull c) {
    ull r; asm("fma.rn.f32x2 %0, %1, %2, %3;" : "=l"(r) : "l"(a), "l"(b), "l"(c)); return r;
}
__device__ __forceinline__ float frcpa(float x) {
    float r; asm("rcp.approx.f32 %0, %1;" : "=f"(r) : "f"(x)); return r;
}

__device__ __forceinline__ float2 cmulf(float2 a, float2 b) {
    return make_float2(a.x * b.x - a.y * b.y, a.x * b.y + a.y * b.x);
}
// packed complex add: one FADD2 instead of two FADD
__device__ __forceinline__ float2 cadd(float2 a, float2 b) {
    union { float2 f; ull u; } A, B, R;
    A.f = a; B.f = b;
    asm("add.rn.f32x2 %0, %1, %2;" : "=l"(R.u) : "l"(A.u), "l"(B.u));
    return R.f;
}
// a - b == fma(b, -1, a) with single rounding -> bit-identical to a-b
__device__ __forceinline__ float2 csub(float2 a, float2 b) {
    union { float2 f; ull u; } A, B, R;
    A.f = a; B.f = b;
    asm("fma.rn.f32x2 %0, %1, %2, %3;"
        : "=l"(R.u) : "l"(B.u), "l"(0xBF800000BF800000ULL), "l"(A.u));
    return R.f;
}
__device__ __forceinline__ float2 cmulF(float2 v, float2 wn, float2 wr) {
    return make_float2(v.x * wn.x + v.y * wr.x, v.x * wn.y + v.y * wr.y);
}

template<bool FWD> __device__ __forceinline__ float2 mul_j(float2 a) {
    return FWD ? make_float2(a.y, -a.x) : make_float2(-a.y, a.x);
}
template<bool FWD> __device__ __forceinline__ float2 mul_w1(float2 a) {
    const float C = 0.70710678118654752f;
    return FWD ? make_float2(C * (a.x + a.y), C * (a.y - a.x))
               : make_float2(C * (a.x - a.y), C * (a.x + a.y));
}
template<bool FWD> __device__ __forceinline__ float2 mul_w3(float2 a) {
    const float C = 0.70710678118654752f;
    return FWD ? make_float2(C * (a.y - a.x), -C * (a.x + a.y))
               : make_float2(-C * (a.x + a.y), C * (a.x - a.y));
}

template<bool FWD>
__device__ __forceinline__ void fft8(float2* v) {
    float2 t0 = cadd(v[0], v[4]), t4 = csub(v[0], v[4]);
    float2 t1 = cadd(v[1], v[5]), t5 = mul_w1<FWD>(csub(v[1], v[5]));
    float2 t2 = cadd(v[2], v[6]), t6 = mul_j<FWD>(csub(v[2], v[6]));
    float2 t3 = cadd(v[3], v[7]), t7 = mul_w3<FWD>(csub(v[3], v[7]));
    float2 u0 = cadd(t0, t2), u2 = csub(t0, t2);
    float2 u1 = cadd(t1, t3), u3 = mul_j<FWD>(csub(t1, t3));
    float2 u4 = cadd(t4, t6), u6 = csub(t4, t6);
    float2 u5 = cadd(t5, t7), u7 = mul_j<FWD>(csub(t5, t7));
    v[0] = cadd(u0, u1); v[4] = csub(u0, u1);
    v[2] = cadd(u2, u3); v[6] = csub(u2, u3);
    v[1] = cadd(u4, u5); v[5] = csub(u4, u5);
    v[3] = cadd(u6, u7); v[7] = csub(u6, u7);
}

__device__ __forceinline__ void fft8_z4(const float2* a, float2* v) {
    float2 t0 = a[0], t4 = a[0];
    float2 t1 = a[1], t5 = mul_w1<true>(a[1]);
    float2 t2 = a[2], t6 = mul_j<true>(a[2]);
    float2 t3 = a[3], t7 = mul_w3<true>(a[3]);
    float2 u0 = cadd(t0, t2), u2 = csub(t0, t2);
    float2 u1 = cadd(t1, t3), u3 = mul_j<true>(csub(t1, t3));
    float2 u4 = cadd(t4, t6), u6 = csub(t4, t6);
    float2 u5 = cadd(t5, t7), u7 = mul_j<true>(csub(t5, t7));
    v[0] = cadd(u0, u1); v[4] = csub(u0, u1);
    v[2] = cadd(u2, u3); v[6] = csub(u2, u3);
    v[1] = cadd(u4, u5); v[5] = csub(u4, u5);
    v[3] = cadd(u6, u7); v[7] = csub(u6, u7);
}

__device__ __forceinline__ void fft8_lo4(const float2* v, float2* o) {
    float2 t0 = cadd(v[0], v[4]), t4 = csub(v[0], v[4]);
    float2 t1 = cadd(v[1], v[5]), t5 = mul_w1<false>(csub(v[1], v[5]));
    float2 t2 = cadd(v[2], v[6]), t6 = mul_j<false>(csub(v[2], v[6]));
    float2 t3 = cadd(v[3], v[7]), t7 = mul_w3<false>(csub(v[3], v[7]));
    float2 u0 = cadd(t0, t2);
    float2 u1 = cadd(t1, t3);
    float2 u2 = csub(t0, t2);
    float2 u3 = mul_j<false>(csub(t1, t3));
    float2 u4 = cadd(t4, t6);
    float2 u5 = cadd(t5, t7);
    float2 u6 = csub(t4, t6);
    float2 u7 = mul_j<false>(csub(t5, t7));
    o[0] = cadd(u0, u1); o[1] = cadd(u4, u5);
    o[2] = cadd(u2, u3); o[3] = cadd(u6, u7);
}

template<bool FWD>
__device__ __forceinline__ void fft4(float2* v) {
    float2 t0 = cadd(v[0], v[2]), t2 = csub(v[0], v[2]);
    float2 t1 = cadd(v[1], v[3]), t3 = mul_j<FWD>(csub(v[1], v[3]));
    v[0] = cadd(t0, t1); v[2] = csub(t0, t1);
    v[1] = cadd(t2, t3); v[3] = csub(t2, t3);
}

template<bool INV>
__device__ __forceinline__ void twapply8(float2* v, float4 W1, float4 W2, float4 W4) {
    float2 w1n, w1r, w2n, w2r, w4n, w4r;
    if (!INV) {
        w1n = make_float2(W1.x, W1.y); w1r = make_float2(W1.z, W1.w);
        w2n = make_float2(W2.x, W2.y); w2r = make_float2(W2.z, W2.w);
        w4n = make_float2(W4.x, W4.y); w4r = make_float2(W4.z, W4.w);
    } else {
        w1n = make_float2(W1.x, -W1.y); w1r = make_float2(-W1.z, W1.w);
        w2n = make_float2(W2.x, -W2.y); w2r = make_float2(-W2.z, W2.w);
        w4n = make_float2(W4.x, -W4.y); w4r = make_float2(-W4.z, W4.w);
    }
    float2 w3n = cmulF(w2n, w1n, w1r); float2 w3r = make_float2(-w3n.y, w3n.x);
    float2 w5n = cmulF(w4n, w1n, w1r); float2 w5r = make_float2(-w5n.y, w5n.x);
    float2 w6n = cmulF(w4n, w2n, w2r); float2 w6r = make_float2(-w6n.y, w6n.x);
    float2 w7n = cmulF(w4n, w3n, w3r); float2 w7r = make_float2(-w7n.y, w7n.x);
    v[1] = cmulF(v[1], w1n, w1r); v[2] = cmulF(v[2], w2n, w2r); v[3] = cmulF(v[3], w3n, w3r);
    v[4] = cmulF(v[4], w4n, w4r); v[5] = cmulF(v[5], w5n, w5r); v[6] = cmulF(v[6], w6n, w6r);
    v[7] = cmulF(v[7], w7n, w7r);
}

template<int NS, bool INV>
__device__ __forceinline__ void stage_ip(float4* s, int t, int tS) {
    float2 v0[8], v1[8];
#pragma unroll
    for (int r = 0; r < 8; r++) {
        float4 z = s[tS + 256 * r];
        v0[r] = make_float2(z.x, z.y);
        v1[r] = make_float2(z.z, z.w);
    }
    int base0 = (2 * t) & (NS - 1);
    {
        float4 W1a = g_twd[4 * NS + base0],     W2a = g_twd[2 * NS + base0],     W4a = g_twd[NS + base0];
        float4 W1b = g_twd[4 * NS + base0 + 1], W2b = g_twd[2 * NS + base0 + 1], W4b = g_twd[NS + base0 + 1];
        twapply8<INV>(v0, W1a, W2a, W4a);
        twapply8<INV>(v1, W1b, W2b, W4b);
    }
    fft8<!INV>(v0); fft8<!INV>(v1);
    __syncthreads();
    int eBase = ((2 * t - base0) << 2) + (base0 >> 1);
#pragma unroll
    for (int r = 0; r < 8; r++)
        s[SW4(eBase + (NS >> 1) * r)] = make_float4(v0[r].x, v0[r].y, v1[r].x, v1[r].y);
    __syncthreads();
}

__device__ __forceinline__ float2 pwone(float2 z, float2 zm, float2 K0k, float2 K1k) {
    float2 u0  = make_float2(0.5f * (z.x + zm.x), 0.5f * (z.y - zm.y));
    float2 iu1 = make_float2(0.5f * (z.x - zm.x), 0.5f * (z.y + zm.y));
    float2 u1  = make_float2(iu1.y, -iu1.x);
    float2 y0 = cmulf(u0, K0k);
    float2 y1 = cmulf(u1, K1k);
    return make_float2(y0.x - y1.y, y0.y + y1.x);
}

__device__ __forceinline__ void inv_stage0_pw_ip(float4* s, int t, int tS,
                                                 const float4* K0, const float4* K1) {
    const float2* sF2 = reinterpret_cast<const float2*>(s);
    float2 v0[8], v1[8];
    int sA0 = SW4(2048 - t);
    int sB0 = SW4(2047 - t);
#pragma unroll
    for (int r = 0; r < 8; r++) {
        float4 z4 = s[tS + 256 * r];
        float2 z1 = make_float2(z4.x, z4.y);
        float2 z2 = make_float2(z4.z, z4.w);
        int e = t + 256 * r;
        float2 zm1 = (e == 0) ? z1 : sF2[(sA0 - 256 * r) * 2];
        float2 zm2 = sF2[(sB0 - 256 * r) * 2 + 1];
        float4 k0 = K0[e];
        float4 k1 = K1[e];
        v0[r] = pwone(z1, zm1, make_float2(k0.x, k0.y), make_float2(k1.x, k1.y));
        v1[r] = pwone(z2, zm2, make_float2(k0.z, k0.w), make_float2(k1.z, k1.w));
    }
    fft8<false>(v0); fft8<false>(v1);
    __syncthreads();
#pragma unroll
    for (int m = 0; m < 4; m++) {
        s[SW4(8 * t + m)]     = make_float4(v0[2*m].x, v0[2*m].y, v0[2*m+1].x, v0[2*m+1].y);
        s[SW4(8 * t + 4 + m)] = make_float4(v1[2*m].x, v1[2*m].y, v1[2*m+1].x, v1[2*m+1].y);
    }
    __syncthreads();
}

__global__ void init_twd_kernel() {
    int i = blockIdx.x * blockDim.x + threadIdx.x;
    if (i >= LFFT) return;
    if (i == 0) { g_twd[0] = make_float4(1.0f, 0.0f, 0.0f, 1.0f); return; }
    int k = 31 - __clz(i);
    int Ns = 1 << k;
    int base = i - Ns;
    float ang = -PI_F * (float)base / (float)Ns;
    float s, c;
    sincosf(ang, &s, &c);
    g_twd[i] = make_float4(c, s, -s, c);
}

__global__ void pad_kernel() {}

__global__ void __launch_bounds__(256) t1_kernel(const float* __restrict__ u) {
    __shared__ float2 tile[32][33];
    int pt = blockIdx.x * 32;
    int rt = blockIdx.y * 32;
    int tx = threadIdx.x & 31, ty = threadIdx.x >> 5;
    const float2* uf2 = reinterpret_cast<const float2*>(u);
#pragma unroll
    for (int i = 0; i < 4; i++) {
        int row = ty + i * 8;
        tile[row][tx] = uf2[(size_t)(rt + row) * NPAIR + pt + tx];
    }
    __syncthreads();
    int b = rt >> 11, l0 = rt & (LSEQ - 1);
    float2* ut2 = reinterpret_cast<float2*>(g_ut);
#pragma unroll
    for (int i = 0; i < 4; i++) {
        int p = pt + ty + i * 8;
        ut2[((size_t)(b * NPAIR + p)) * LSEQ + l0 + tx] = tile[tx][ty + i * 8];
    }
}

__global__ void __launch_bounds__(256) t2_kernel(float* __restrict__ out) {
    __shared__ float2 tile[32][33];
    int pt = blockIdx.x * 32;
    int rt = blockIdx.y * 32;
    int tx = threadIdx.x & 31, ty = threadIdx.x >> 5;
    int b = rt >> 11, l0 = rt & (LSEQ - 1);
    const float2* yt2 = reinterpret_cast<const float2*>(g_yt);
#pragma unroll
    for (int i = 0; i < 4; i++) {
        int p = pt + ty + i * 8;
        tile[ty + i * 8][tx] = yt2[((size_t)(b * NPAIR + p)) * LSEQ + l0 + tx];
    }
    __syncthreads();
    float2* of2 = reinterpret_cast<float2*>(out);
#pragma unroll
    for (int i = 0; i < 4; i++) {
        int row = ty + i * 8;
        of2[(size_t)(rt + row) * NPAIR + pt + tx] = tile[tx][row];
    }
}

// ---------------------------------------------------------------------------
// khat FFT helpers (unchanged structure; cadd/csub now packed)
// ---------------------------------------------------------------------------
template<bool FWD>
__device__ float2* fft4096_r8(float2* src, float2* dst, int tid, int nth) {
#pragma unroll
    for (int s = 0; s < 4; s++) {
        const int Ns = 1 << (3 * s);
        for (int j = tid; j < 512; j += nth) {
            float2 v[8];
#pragma unroll
            for (int r = 0; r < 8; r++) v[r] = src[SWZ(j + r * 512)];
            const int base = j & (Ns - 1);
            if (Ns > 1) {
                float4 T1 = g_twd[4 * Ns + base];
                float4 T2 = g_twd[2 * Ns + base];
                float4 T4 = g_twd[Ns + base];
                float2 w1 = make_float2(T1.x, FWD ? T1.y : -T1.y);
                float2 w2 = make_float2(T2.x, FWD ? T2.y : -T2.y);
                float2 w4 = make_float2(T4.x, FWD ? T4.y : -T4.y);
                float2 w3 = cmulf(w1, w2), w5 = cmulf(w1, w4);
                float2 w6 = cmulf(w2, w4), w7 = cmulf(w3, w4);
                v[1] = cmulf(v[1], w1); v[2] = cmulf(v[2], w2); v[3] = cmulf(v[3], w3);
                v[4] = cmulf(v[4], w4); v[5] = cmulf(v[5], w5); v[6] = cmulf(v[6], w6);
                v[7] = cmulf(v[7], w7);
            }
            fft8<FWD>(v);
            const int idxD = ((j - base) << 3) + base;
#pragma unroll
            for (int r = 0; r < 8; r++) dst[SWZ(idxD + r * Ns)] = v[r];
        }
        __syncthreads();
        float2* t = src; src = dst; dst = t;
    }
    return src;
}

__device__ float2* ifft2048_mr(float2* src, float2* dst, int tid, int nth) {
#pragma unroll
    for (int s = 0; s < 3; s++) {
        const int Ns = 1 << (3 * s);
        for (int j = tid; j < 256; j += nth) {
            float2 v[8];
#pragma unroll
            for (int r = 0; r < 8; r++) v[r] = src[SWZ(j + r * 256)];
            const int base = j & (Ns - 1);
            if (Ns > 1) {
                float4 T1 = g_twd[4 * Ns + base];
                float4 T2 = g_twd[2 * Ns + base];
                float4 T4 = g_twd[Ns + base];
                float2 w1 = make_float2(T1.x, -T1.y);
                float2 w2 = make_float2(T2.x, -T2.y);
                float2 w4 = make_float2(T4.x, -T4.y);
                float2 w3 = cmulf(w1, w2), w5 = cmulf(w1, w4);
                float2 w6 = cmulf(w2, w4), w7 = cmulf(w3, w4);
                v[1] = cmulf(v[1], w1); v[2] = cmulf(v[2], w2); v[3] = cmulf(v[3], w3);
                v[4] = cmulf(v[4], w4); v[5] = cmulf(v[5], w5); v[6] = cmulf(v[6], w6);
                v[7] = cmulf(v[7], w7);
            }
            fft8<false>(v);
            const int idxD = ((j - base) << 3) + base;
#pragma unroll
            for (int r = 0; r < 8; r++) dst[SWZ(idxD + r * Ns)] = v[r];
        }
        __syncthreads();
        float2* t = src; src = dst; dst = t;
    }
    for (int j = tid; j < 512; j += nth) {
        float2 v[4];
#pragma unroll
        for (int r = 0; r < 4; r++) v[r] = src[SWZ(j + r * 512)];
        float4 T1 = g_twd[1024 + j];
        float4 T2 = g_twd[512 + j];
        float2 w1 = make_float2(T1.x, -T1.y);
        float2 w2 = make_float2(T2.x, -T2.y);
        float2 w3 = cmulf(w1, w2);
        v[1] = cmulf(v[1], w1); v[2] = cmulf(v[2], w2); v[3] = cmulf(v[3], w3);
        fft4<false>(v);
#pragma unroll
        for (int r = 0; r < 4; r++) dst[SWZ(j + r * 512)] = v[r];
    }
    __syncthreads();
    return dst;
}

// ---------------------------------------------------------------------------
// khat kernel: Cauchy inner loop rewritten with packed f32x2 (k-pairs).
// ---------------------------------------------------------------------------
__global__ void __launch_bounds__(512, 2) khat_kernel(
    const float* __restrict__ pr, const float* __restrict__ qr,
    const float* __restrict__ lamr, const float* __restrict__ Br,
    const float* __restrict__ Ctr, const float* __restrict__ logstep) {
    extern __shared__ float2 sm[];
    float2* buf0 = sm;
    float2* buf1 = sm + LFFT;

    __shared__ float2 w00[NSTATE], w01[NSTATE], w10[NSTATE], w11[NSTATE];
    __shared__ float2 lams[NSTATE];
    __shared__ float s_inv2step;

    int d = blockIdx.x;
    int tid = threadIdx.x;

    if (tid < NSTATE) {
        int n = tid;
        float2 p  = make_float2(pr[2*n],  pr[2*n+1]);
        float2 qc = make_float2(qr[2*n], -qr[2*n+1]);
        float2 lm = make_float2(lamr[2*n], lamr[2*n+1]);
        float2 Bv = make_float2(Br[(d*NSTATE+n)*2],  Br[(d*NSTATE+n)*2+1]);
        float2 Cc = make_float2(Ctr[(d*NSTATE+n)*2], -Ctr[(d*NSTATE+n)*2+1]);
        w00[n] = cmulf(Cc, Bv);
        w01[n] = cmulf(Cc, p);
        w10[n] = cmulf(qc, Bv);
        w11[n] = cmulf(qc, p);
        lams[n] = lm;
    }
    if (tid == 0) s_inv2step = 2.0f * expf(-logstep[d]);
    __syncthreads();

    float inv2step = s_inv2step;
    {
        // 4 frequency points as 2 packed pairs: pair j = (k=tid+1024j, k=tid+512+1024j)
        float ts[4];
        ull Gp[2];
        {
            float gim[4];
#pragma unroll
            for (int kk = 0; kk < 4; kk++) {
                int l = tid + kk * 512;
                float theta = (PI_F / (float)LSEQ) * (float)l;
                float tt = tanf(theta);
                ts[kk] = tt;
                gim[kk] = -inv2step * tt;
            }
            Gp[0] = pk(gim[0], gim[1]);
            Gp[1] = pk(gim[2], gim[3]);
        }
        ull a00x[2] = {0, 0}, a00y[2] = {0, 0};
        ull a01x[2] = {0, 0}, a01y[2] = {0, 0};
        ull a10x[2] = {0, 0}, a10y[2] = {0, 0};
        ull a11x[2] = {0, 0}, a11y[2] = {0, 0};
        const ull NEG1 = 0xBF800000BF800000ULL;

        for (int n = 0; n < NSTATE; n++) {
            float2 lw  = lams[n];
            float2 v00 = w00[n], v01 = w01[n], v10 = w10[n], v11 = w11[n];
            float dr = -lw.x;
            ull nlwy = pk(-lw.y, -lw.y);
            ull drp  = pk(dr, dr);
            ull drsq = pk(dr * dr, dr * dr);
            ull x00 = pk(v00.x, v00.x), y00 = pk(v00.y, v00.y);
            ull x01 = pk(v01.x, v01.x), y01 = pk(v01.y, v01.y);
            ull x10 = pk(v10.x, v10.x), y10 = pk(v10.y, v10.y);
            ull x11 = pk(v11.x, v11.x), y11 = pk(v11.y, v11.y);
#pragma unroll
            for (int j = 0; j < 2; j++) {
                ull dip = padd(Gp[j], nlwy);          // di = gim - lw.y (pair)
                ull mag = pfma(dip, dip, drsq);       // dr^2 + di^2
                float m0, m1;
                upk(mag, m0, m1);
                ull invp = pk(frcpa(m0), frcpa(m1));
                ull sx  = pmul(drp, invp);            // Re(r)
                ull ty  = pmul(dip, invp);            // -Im(r)
                ull nty = pmul(ty, NEG1);             // Im(r)
                a00x[j] = pfma(x00, sx, a00x[j]); a00x[j] = pfma(y00, ty,  a00x[j]);
                a00y[j] = pfma(y00, sx, a00y[j]); a00y[j] = pfma(x00, nty, a00y[j]);
                a01x[j] = pfma(x01, sx, a01x[j]); a01x[j] = pfma(y01, ty,  a01x[j]);
                a01y[j] = pfma(y01, sx, a01y[j]); a01y[j] = pfma(x01, nty, a01y[j]);
                a10x[j] = pfma(x10, sx, a10x[j]); a10x[j] = pfma(y10, ty,  a10x[j]);
                a10y[j] = pfma(y10, sx, a10y[j]); a10y[j] = pfma(x10, nty, a10y[j]);
                a11x[j] = pfma(x11, sx, a11x[j]); a11x[j] = pfma(y11, ty,  a11x[j]);
                a11y[j] = pfma(y11, sx, a11y[j]); a11y[j] = pfma(x11, nty, a11y[j]);
            }
        }

#pragma unroll
        for (int j = 0; j < 2; j++) {
            float x0, x1, y0, y1;
            float2 A00[2], A01[2], A10[2], A11[2];
            upk(a00x[j], x0, x1); upk(a00y[j], y0, y1);
            A00[0] = make_float2(x0, y0); A00[1] = make_float2(x1, y1);
            upk(a01x[j], x0, x1); upk(a01y[j], y0, y1);
            A01[0] = make_float2(x0, y0); A01[1] = make_float2(x1, y1);
            upk(a10x[j], x0, x1); upk(a10y[j], y0, y1);
            A10[0] = make_float2(x0, y0); A10[1] = make_float2(x1, y1);
            upk(a11x[j], x0, x1); upk(a11y[j], y0, y1);
            A11[0] = make_float2(x0, y0); A11[1] = make_float2(x1, y1);
#pragma unroll
            for (int slot = 0; slot < 2; slot++) {
                int kk = 2 * j + slot;
                int l = tid + kk * 512;
                float2 den = make_float2(1.0f + A11[slot].x, A11[slot].y);
                float dinv = __fdividef(1.0f, den.x * den.x + den.y * den.y);
                float2 num = cmulf(A01[slot], A10[slot]);
                float2 frac = make_float2((num.x * den.x + num.y * den.y) * dinv,
                                          (num.y * den.x - num.x * den.y) * dinv);
                float2 inner = make_float2(A00[slot].x - frac.x, A00[slot].y - frac.y);
                float2 c = make_float2(1.0f, -ts[kk]);
                buf0[SWZ(l)] = cmulf(c, inner);
            }
        }
    }
    __syncthreads();

    float2* res = ifft2048_mr(buf0, buf1, tid, 512);
    float2* oth = (res == buf0) ? buf1 : buf0;

    const float invL = 1.0f / (float)LSEQ;
    for (int m = tid; m < LSEQ; m += 512) {
        float kr = res[SWZ((LSEQ - m) & (LSEQ - 1))].x * invL;
        oth[SWZ(m)]        = make_float2(kr, 0.0f);
        oth[SWZ(m + LSEQ)] = make_float2(0.0f, 0.0f);
    }
    __syncthreads();

    float2* res2 = fft4096_r8<true>(oth, res, tid, 512);
    const float invF = 1.0f / (float)LFFT;
    float2* KH = reinterpret_cast<float2*>(g_Khat4);
    for (int k = tid; k < LFFT; k += 512) {
        float2 v = res2[SWZ(k)];
        KH[d * LFFT + k] = make_float2(v.x * invF, v.y * invF);
    }
}

// ---------------------------------------------------------------------------
// conv kernel (R4 structure; butterflies now use packed cadd/csub)
// ---------------------------------------------------------------------------
__global__ void __launch_bounds__(256, 2) conv_kernel(const float* __restrict__ Dvec) {
    extern __shared__ float4 s[];

    int t    = threadIdx.x;
    int blk  = blockIdx.x;
    int pair = blk & (NPAIR - 1);
    int b    = blk >> 8;
    int d0   = pair * 2;
    int tS   = SW4(t);

    const float4* ut = g_ut + ((size_t)(b * NPAIR + pair)) * (LSEQ / 2);
    float4*       yt = g_yt + ((size_t)(b * NPAIR + pair)) * (LSEQ / 2);

    float4 uin[4];
    {
        float2 a[4], bb[4], v0[8], v1[8];
#pragma unroll
        for (int r = 0; r < 4; r++) {
            uin[r] = ut[t + 256 * r];
            a[r]  = make_float2(uin[r].x, uin[r].y);
            bb[r] = make_float2(uin[r].z, uin[r].w);
        }
        fft8_z4(a, v0);
        fft8_z4(bb, v1);
#pragma unroll
        for (int m = 0; m < 4; m++) {
            s[SW4(8 * t + m)]     = make_float4(v0[2*m].x, v0[2*m].y, v0[2*m+1].x, v0[2*m+1].y);
            s[SW4(8 * t + 4 + m)] = make_float4(v1[2*m].x, v1[2*m].y, v1[2*m+1].x, v1[2*m+1].y);
        }
        __syncthreads();
    }

    stage_ip<8,   false>(s, t, tS);
    stage_ip<64,  false>(s, t, tS);
    stage_ip<512, false>(s, t, tS);

    const float4* K0 = g_Khat4 + (size_t)d0 * (LFFT / 2);
    const float4* K1 = K0 + (LFFT / 2);
    inv_stage0_pw_ip(s, t, tS, K0, K1);

    stage_ip<8,  true>(s, t, tS);
    stage_ip<64, true>(s, t, tS);

    {
        float2 v0[8], v1[8], o0[4], o1[4];
#pragma unroll
        for (int r = 0; r < 8; r++) {
            float4 z = s[tS + 256 * r];
            v0[r] = make_float2(z.x, z.y);
            v1[r] = make_float2(z.z, z.w);
        }
        float4 W1a = g_twd[2048 + 2*t], W2a = g_twd[1024 + 2*t], W4a = g_twd[512 + 2*t];
        float4 W1b = g_twd[2049 + 2*t], W2b = g_twd[1025 + 2*t], W4b = g_twd[513 + 2*t];
        twapply8<true>(v0, W1a, W2a, W4a);
        twapply8<true>(v1, W1b, W2b, W4b);
        fft8_lo4(v0, o0);
        fft8_lo4(v1, o1);

        float D0 = Dvec[d0], D1 = Dvec[d0 + 1];
#pragma unroll
        for (int r = 0; r < 4; r++) {
            yt[t + 256 * r] = make_float4(
                o0[r].x + D0 * uin[r].x, o0[r].y + D1 * uin[r].y,
                o1[r].x + D0 * uin[r].z, o1[r].y + D1 * uin[r].w);
        }
    }
}

// ---------------------------------------------------------------------------
// Inputs: u, p_ri, q_ri, lam_ri, B_ri, Ct_ri, D, log_step
// khat at launch index 3 for ncu this round.
// ---------------------------------------------------------------------------
extern "C" void kernel_launch(void* const* d_in, const int* in_sizes, int n_in,
                              void* d_out, int out_size) {
    const float* u   = (const float*)d_in[0];
    const float* pr  = (const float*)d_in[1];
    const float* qr  = (const float*)d_in[2];
    const float* lam = (const float*)d_in[3];
    const float* Br  = (const float*)d_in[4];
    const float* Ct  = (const float*)d_in[5];
    const float* Dv  = (const float*)d_in[6];
    const float* ls  = (const float*)d_in[7];
    float* out = (float*)d_out;

    const int smem_khat = 2 * LFFT * (int)sizeof(float2);   // 64 KB
    const int smem_conv = 2048 * (int)sizeof(float4);       // 32 KB
    cudaFuncSetAttribute(khat_kernel, cudaFuncAttributeMaxDynamicSharedMemorySize, smem_khat);
    cudaFuncSetAttribute(conv_kernel, cudaFuncAttributeMaxDynamicSharedMemorySize, smem_conv);

    t1_kernel<<<dim3(NPAIR / 32, NBATCH * LSEQ / 32), 256>>>(u);            // 0
    init_twd_kernel<<<LFFT / 512, 512>>>();                                  // 1
    pad_kernel<<<1, 32>>>();                                                 // 2
    khat_kernel<<<DMODEL, 512, smem_khat>>>(pr, qr, lam, Br, Ct, ls);        // 3  <- ncu target
    conv_kernel<<<NBATCH * NPAIR, 256, smem_conv>>>(Dv);                     // 4
    t2_kernel<<<dim3(NPAIR / 32, NBATCH * LSEQ / 32), 256>>>(out);           // 5
}